// round 3
// baseline (speedup 1.0000x reference)
#include <cuda_runtime.h>
#include <math.h>

#define NN 10000
#define NE 160000

typedef unsigned long long u64;

// ---------------- device scratch (static, allocation-free) ----------------
__device__ float g_t[NN * 16];
__device__ float g_qW[NN * 8];
__device__ float g_h1k[(size_t)NE * 128];
__device__ float g_h2k[(size_t)NE * 128];
__device__ float g_h1v[(size_t)NE * 128];
__device__ float g_h2v[(size_t)NE * 128];
__device__ float g_WK[(size_t)NE * 512];
__device__ float g_WV[(size_t)NE * 1024];
__device__ float g_vbuf[(size_t)NE * 16];
__device__ float g_logit[NE];
__device__ float g_m[NN];
__device__ float g_z[NN];
__device__ float g_agg[NN * 16];
__device__ float g_colsum[64];
__device__ float g_colsumsq[64];
__device__ float g_outpre[NN * 64];

// ---------------- helpers ----------------
__device__ __forceinline__ void atomicMaxF(float* addr, float v) {
    if (v >= 0.f)
        atomicMax((int*)addr, __float_as_int(v));
    else
        atomicMin((unsigned int*)addr, __float_as_uint(v));
}

__device__ __forceinline__ u64 pack2(float lo, float hi) {
    u64 r;
    asm("mov.b64 %0, {%1, %2};" : "=l"(r) : "f"(lo), "f"(hi));
    return r;
}
__device__ __forceinline__ u64 ffma2(u64 a, u64 b, u64 c) {
    u64 d;
    asm("fma.rn.f32x2 %0, %1, %2, %3;" : "=l"(d) : "l"(a), "l"(b), "l"(c));
    return d;
}
__device__ __forceinline__ void unpack2(u64 v, float& lo, float& hi) {
    asm("mov.b64 {%0, %1}, %2;" : "=f"(lo), "=f"(hi) : "l"(v));
}

// ---------------- init ----------------
__global__ void init_kernel() {
    int i = blockIdx.x * 256 + threadIdx.x;
    if (i < NN) { g_m[i] = -INFINITY; g_z[i] = 0.f; }
    if (i < NN * 16) g_agg[i] = 0.f;
    if (i < 64) { g_colsum[i] = 0.f; g_colsumsq[i] = 0.f; }
}

// ---------------- node linears: t = nd@Wi/8 ; qW = ((t@Wq)/4)@Wd/8 ----------------
__global__ __launch_bounds__(128) void node_kernel(
    const float* __restrict__ node_data, const float* __restrict__ W_input,
    const float* __restrict__ W_query, const float* __restrict__ W_dot)
{
    __shared__ float Wi[64 * 16];
    __shared__ float Wq[16 * 8];
    __shared__ float Wd[64];
    __shared__ float tsh[8][16];
    __shared__ float qsh[8][8];
    int tid = threadIdx.x;
    for (int i = tid; i < 1024; i += 128) Wi[i] = W_input[i];
    if (tid < 128) Wq[tid] = W_query[tid];
    if (tid < 64) Wd[tid] = W_dot[tid];
    __syncthreads();

    int n_loc = tid >> 4, c = tid & 15;
    int n = blockIdx.x * 8 + n_loc;
    float tv = 0.f;
    if (n < NN) {
        const float* nd = node_data + (size_t)n * 64;
        #pragma unroll 8
        for (int i = 0; i < 64; i++) tv += nd[i] * Wi[i * 16 + c];
        tv *= 0.125f;
        g_t[n * 16 + c] = tv;
    }
    tsh[n_loc][c] = tv;
    __syncthreads();

    if (tid < 64) {
        int nl = tid >> 3, b = tid & 7;
        float qv = 0.f;
        #pragma unroll
        for (int a = 0; a < 16; a++) qv += tsh[nl][a] * Wq[a * 8 + b];
        qsh[nl][b] = qv * 0.25f;
    }
    __syncthreads();
    if (tid < 64) {
        int nl = tid >> 3, b = tid & 7;
        int n2 = blockIdx.x * 8 + nl;
        if (n2 < NN) {
            float s = 0.f;
            #pragma unroll
            for (int a = 0; a < 8; a++) s += qsh[nl][a] * Wd[a * 8 + b];
            g_qW[n2 * 8 + b] = s * 0.125f;
        }
    }
}

// ---------------- tiled SGEMM with packed f32x2 FMA ----------------
// BM=BN=128, BK=32, 256 threads, 8x8 microtile (4 packed col-pairs).
template <bool RELU>
__global__ __launch_bounds__(256) void gemm_kernel(
    const float* __restrict__ A, const float* __restrict__ B,
    const float* __restrict__ bias, float* __restrict__ C,
    int M, int N, int K)
{
    __shared__ float As[32][129];
    __shared__ float Bs[32][128];
    const int tid = threadIdx.x;
    const int m0 = blockIdx.y * 128;
    const int n0 = blockIdx.x * 128;
    const int tr = tid >> 4;  // 0..15
    const int tc = tid & 15;  // 0..15

    u64 acc2[8][4];
    #pragma unroll
    for (int i = 0; i < 8; i++)
        #pragma unroll
        for (int j = 0; j < 4; j++) acc2[i][j] = 0ull;

    for (int k0 = 0; k0 < K; k0 += 32) {
        #pragma unroll
        for (int i = 0; i < 4; i++) {
            int idx = tid + i * 256;
            int row = idx >> 3;
            int q = idx & 7;
            float4 av = *(const float4*)(A + (size_t)(m0 + row) * K + k0 + q * 4);
            As[q * 4 + 0][row] = av.x;
            As[q * 4 + 1][row] = av.y;
            As[q * 4 + 2][row] = av.z;
            As[q * 4 + 3][row] = av.w;
        }
        #pragma unroll
        for (int i = 0; i < 4; i++) {
            int idx = tid + i * 256;
            int kk = idx >> 5;
            int c4 = idx & 31;
            *(float4*)(&Bs[kk][c4 * 4]) =
                *(const float4*)(B + (size_t)(k0 + kk) * N + n0 + c4 * 4);
        }
        __syncthreads();
        #pragma unroll
        for (int kk = 0; kk < 32; kk++) {
            // b: 4 packed pairs straight out of smem (8-byte aligned)
            const u64* bp = (const u64*)(&Bs[kk][tc * 8]);
            u64 b2[4];
            #pragma unroll
            for (int j = 0; j < 4; j++) b2[j] = bp[j];
            // a: 8 scalars, replicated into pairs
            #pragma unroll
            for (int i = 0; i < 8; i++) {
                float av = As[kk][tr * 8 + i];
                u64 a2 = pack2(av, av);
                #pragma unroll
                for (int j = 0; j < 4; j++)
                    acc2[i][j] = ffma2(a2, b2[j], acc2[i][j]);
            }
        }
        __syncthreads();
    }

    float bb[8];
    #pragma unroll
    for (int j = 0; j < 8; j++) bb[j] = bias[n0 + tc * 8 + j];
    #pragma unroll
    for (int i = 0; i < 8; i++) {
        int row = m0 + tr * 8 + i;
        float v[8];
        #pragma unroll
        for (int j = 0; j < 4; j++) {
            float lo, hi;
            unpack2(acc2[i][j], lo, hi);
            float x0 = lo + bb[2 * j];
            float x1 = hi + bb[2 * j + 1];
            v[2 * j]     = RELU ? fmaxf(x0, 0.f) : x0;
            v[2 * j + 1] = RELU ? fmaxf(x1, 0.f) : x1;
        }
        *(float4*)(C + (size_t)row * N + n0 + tc * 8) = make_float4(v[0], v[1], v[2], v[3]);
        *(float4*)(C + (size_t)row * N + n0 + tc * 8 + 4) = make_float4(v[4], v[5], v[6], v[7]);
    }
}

// ---------------- per-edge bilinear contraction + logits (warp per edge) ----------------
__global__ __launch_bounds__(256) void uv_kernel(
    const int* __restrict__ ei, const float* __restrict__ sh)
{
    int gw = (blockIdx.x * 256 + threadIdx.x) >> 5;
    int lane = threadIdx.x & 31;
    if (gw >= NE) return;
    int e = gw;
    int src = ei[e];
    int dst = ei[NE + e];

    // u[as] = t[src,a]*sh[e,s] / sqrt(64);  lane owns as = lane, lane+32
    float shl = sh[e * 4 + (lane & 3)];
    float u_lo = g_t[src * 16 + (lane >> 2)] * shl * 0.125f;
    float u_hi = g_t[src * 16 + 8 + (lane >> 2)] * shl * 0.125f;

    // k partial (C_KEY=8): wk layout [as][b], as index = a*4+s
    const float* wkp = g_WK + (size_t)e * 512;
    float4 ka0 = *(const float4*)(wkp + lane * 8);
    float4 ka1 = *(const float4*)(wkp + lane * 8 + 4);
    float4 kb0 = *(const float4*)(wkp + 256 + lane * 8);
    float4 kb1 = *(const float4*)(wkp + 256 + lane * 8 + 4);
    float kacc[8];
    kacc[0] = u_lo * ka0.x + u_hi * kb0.x;
    kacc[1] = u_lo * ka0.y + u_hi * kb0.y;
    kacc[2] = u_lo * ka0.z + u_hi * kb0.z;
    kacc[3] = u_lo * ka0.w + u_hi * kb0.w;
    kacc[4] = u_lo * ka1.x + u_hi * kb1.x;
    kacc[5] = u_lo * ka1.y + u_hi * kb1.y;
    kacc[6] = u_lo * ka1.z + u_hi * kb1.z;
    kacc[7] = u_lo * ka1.w + u_hi * kb1.w;

    // logit on partials (dot with qW is linear -> reduce one scalar, not 8)
    const float* qwp = g_qW + dst * 8;
    float lp = 0.f;
    #pragma unroll
    for (int b = 0; b < 8; b++) lp += kacc[b] * qwp[b];
    #pragma unroll
    for (int off = 16; off; off >>= 1) lp += __shfl_xor_sync(0xffffffffu, lp, off);

    // v (C_OTP=16)
    const float* wvp = g_WV + (size_t)e * 1024;
    float vacc[16];
    {
        const float* p = wvp + lane * 16;
        #pragma unroll
        for (int q = 0; q < 4; q++) {
            float4 w = *(const float4*)(p + q * 4);
            vacc[q * 4 + 0] = u_lo * w.x;
            vacc[q * 4 + 1] = u_lo * w.y;
            vacc[q * 4 + 2] = u_lo * w.z;
            vacc[q * 4 + 3] = u_lo * w.w;
        }
        p = wvp + 512 + lane * 16;
        #pragma unroll
        for (int q = 0; q < 4; q++) {
            float4 w = *(const float4*)(p + q * 4);
            vacc[q * 4 + 0] += u_hi * w.x;
            vacc[q * 4 + 1] += u_hi * w.y;
            vacc[q * 4 + 2] += u_hi * w.z;
            vacc[q * 4 + 3] += u_hi * w.w;
        }
    }
    #pragma unroll
    for (int off = 16; off; off >>= 1)
        #pragma unroll
        for (int b = 0; b < 16; b++)
            vacc[b] += __shfl_xor_sync(0xffffffffu, vacc[b], off);

    float vout = 0.f;
    #pragma unroll
    for (int b = 0; b < 16; b++) vout = (lane == b) ? vacc[b] : vout;
    if (lane < 16) g_vbuf[(size_t)e * 16 + lane] = vout;
    if (lane == 0) {
        g_logit[e] = lp;
        atomicMaxF(&g_m[dst], lp);
    }
}

// ---------------- softmax numerator + segment sums ----------------
__global__ void attn_agg_kernel(const int* __restrict__ ei)
{
    int e = blockIdx.x * 256 + threadIdx.x;
    if (e >= NE) return;
    int dst = ei[NE + e];
    float p = expf(g_logit[e] - g_m[dst]);
    atomicAdd(&g_z[dst], p);
    const float* v = g_vbuf + (size_t)e * 16;
    float* agg = g_agg + dst * 16;
    #pragma unroll
    for (int c = 0; c < 16; c++) atomicAdd(&agg[c], p * v[c]);
}

// ---------------- output linear + residual + BN stats ----------------
__global__ __launch_bounds__(256) void out_stats_kernel(
    const float* __restrict__ node_data, const float* __restrict__ W_output)
{
    __shared__ float Wsh[16 * 64];
    __shared__ float red[256];
    int tid = threadIdx.x;
    for (int i = tid; i < 1024; i += 256) Wsh[i] = W_output[i];
    __syncthreads();

    int c = tid & 63;
    int r = tid >> 6;  // 0..3
    int n0 = blockIdx.x * 64;
    float lsum = 0.f, lsq = 0.f;
    for (int i = 0; i < 16; i++) {
        int n = n0 + r + i * 4;
        if (n < NN) {
            float zz = g_z[n];
            float inv = zz > 0.f ? 0.25f / zz : 0.f;  // fold /sqrt(16)
            float o = 0.f;
            const float* agg = g_agg + n * 16;
            #pragma unroll
            for (int j = 0; j < 16; j++) o += agg[j] * Wsh[j * 64 + c];
            o = o * inv + node_data[(size_t)n * 64 + c];
            g_outpre[(size_t)n * 64 + c] = o;
            lsum += o;
            lsq += o * o;
        }
    }
    red[tid] = lsum;
    __syncthreads();
    if (r == 0) atomicAdd(&g_colsum[c], red[c] + red[64 + c] + red[128 + c] + red[192 + c]);
    __syncthreads();
    red[tid] = lsq;
    __syncthreads();
    if (r == 0) atomicAdd(&g_colsumsq[c], red[c] + red[64 + c] + red[128 + c] + red[192 + c]);
}

// ---------------- batchnorm finalize ----------------
__global__ void bn_kernel(const float* __restrict__ bnw, const float* __restrict__ bnb,
                          float* __restrict__ out)
{
    int i = blockIdx.x * 256 + threadIdx.x;
    if (i >= NN * 64) return;
    int c = i & 63;
    const float invN = 1.f / NN;
    float mean = g_colsum[c] * invN;
    float var = g_colsumsq[c] * invN - mean * mean;
    out[i] = (g_outpre[i] - mean) * rsqrtf(var + 1e-5f) * bnw[c] + bnb[c];
}

// ---------------- launch ----------------
extern "C" void kernel_launch(void* const* d_in, const int* in_sizes, int n_in,
                              void* d_out, int out_size)
{
    const float* node_data = (const float*)d_in[0];
    const int*   edge_index = (const int*)d_in[1];
    const float* edge_data = (const float*)d_in[2];
    const float* edge_sh   = (const float*)d_in[3];
    const float* W_input = (const float*)d_in[4];
    const float* W_query = (const float*)d_in[5];
    const float* W_dot   = (const float*)d_in[6];
    const float* W_output = (const float*)d_in[7];
    const float* Wk1 = (const float*)d_in[8];
    const float* bk1 = (const float*)d_in[9];
    const float* Wk2 = (const float*)d_in[10];
    const float* bk2 = (const float*)d_in[11];
    const float* Wk3 = (const float*)d_in[12];
    const float* bk3 = (const float*)d_in[13];
    const float* Wv1 = (const float*)d_in[14];
    const float* bv1 = (const float*)d_in[15];
    const float* Wv2 = (const float*)d_in[16];
    const float* bv2 = (const float*)d_in[17];
    const float* Wv3 = (const float*)d_in[18];
    const float* bv3 = (const float*)d_in[19];
    const float* bn_weight = (const float*)d_in[20];
    const float* bn_bias   = (const float*)d_in[21];
    float* out = (float*)d_out;

    void *p_h1k, *p_h2k, *p_h1v, *p_h2v, *p_WK, *p_WV;
    cudaGetSymbolAddress(&p_h1k, g_h1k);
    cudaGetSymbolAddress(&p_h2k, g_h2k);
    cudaGetSymbolAddress(&p_h1v, g_h1v);
    cudaGetSymbolAddress(&p_h2v, g_h2v);
    cudaGetSymbolAddress(&p_WK, g_WK);
    cudaGetSymbolAddress(&p_WV, g_WV);

    init_kernel<<<(NE + 255) / 256, 256>>>();
    node_kernel<<<(NN + 7) / 8, 128>>>(node_data, W_input, W_query, W_dot);

    dim3 g1(1, NE / 128);
    gemm_kernel<true><<<g1, 256>>>(edge_data, Wk1, bk1, (float*)p_h1k, NE, 128, 32);
    gemm_kernel<true><<<g1, 256>>>((const float*)p_h1k, Wk2, bk2, (float*)p_h2k, NE, 128, 128);
    gemm_kernel<true><<<g1, 256>>>(edge_data, Wv1, bv1, (float*)p_h1v, NE, 128, 32);
    gemm_kernel<true><<<g1, 256>>>((const float*)p_h1v, Wv2, bv2, (float*)p_h2v, NE, 128, 128);

    dim3 gk(4, NE / 128);
    gemm_kernel<false><<<gk, 256>>>((const float*)p_h2k, Wk3, bk3, (float*)p_WK, NE, 512, 128);
    dim3 gv(8, NE / 128);
    gemm_kernel<false><<<gv, 256>>>((const float*)p_h2v, Wv3, bv3, (float*)p_WV, NE, 1024, 128);

    uv_kernel<<<NE / 8, 256>>>(edge_index, edge_sh);
    attn_agg_kernel<<<(NE + 255) / 256, 256>>>(edge_index);
    out_stats_kernel<<<(NN + 63) / 64, 256>>>(node_data, W_output);
    bn_kernel<<<(NN * 64 + 255) / 256, 256>>>(bn_weight, bn_bias, out);
}

// round 6
// speedup vs baseline: 1.5561x; 1.5561x over previous
#include <cuda_runtime.h>
#include <cuda_bf16.h>
#include <stdint.h>
#include <math.h>

#define NN 10000
#define NE 160000

// ---------------- device scratch (static, allocation-free) ----------------
__device__ float g_t[NN * 16];
__device__ float g_qW[NN * 8];
__device__ float g_h1k[(size_t)NE * 128];
__device__ float g_h2k[(size_t)NE * 128];
__device__ float g_h1v[(size_t)NE * 128];
__device__ float g_h2v[(size_t)NE * 128];
__device__ float g_WK[(size_t)NE * 512];
__device__ float g_WV[(size_t)NE * 1024];
// transposed, split weights [N, K] bf16
__device__ __nv_bfloat16 g_w1k_h[128 * 32], g_w1k_l[128 * 32];
__device__ __nv_bfloat16 g_w1v_h[128 * 32], g_w1v_l[128 * 32];
__device__ __nv_bfloat16 g_w2k_h[128 * 128], g_w2k_l[128 * 128];
__device__ __nv_bfloat16 g_w2v_h[128 * 128], g_w2v_l[128 * 128];
__device__ __nv_bfloat16 g_w3k_h[512 * 128], g_w3k_l[512 * 128];
__device__ __nv_bfloat16 g_w3v_h[1024 * 128], g_w3v_l[1024 * 128];
// fp32 tail
__device__ float g_vbuf[(size_t)NE * 16];
__device__ float g_logit[NE];
__device__ float g_m[NN];
__device__ float g_z[NN];
__device__ float g_agg[NN * 16];
__device__ float g_colsum[64];
__device__ float g_colsumsq[64];
__device__ float g_outpre[NN * 64];

// ---------------- helpers ----------------
__device__ __forceinline__ void atomicMaxF(float* addr, float v) {
    if (v >= 0.f)
        atomicMax((int*)addr, __float_as_int(v));
    else
        atomicMin((unsigned int*)addr, __float_as_uint(v));
}

__device__ __forceinline__ uint32_t smem_u32(const void* p) {
    uint32_t a;
    asm("{ .reg .u64 t; cvta.to.shared.u64 t, %1; cvt.u32.u64 %0, t; }" : "=r"(a) : "l"(p));
    return a;
}

__device__ __forceinline__ void split2(float x, __nv_bfloat16& h, __nv_bfloat16& l) {
    h = __float2bfloat16(x);
    l = __float2bfloat16(x - __bfloat162float(h));
}

__device__ __forceinline__ void ldm4(uint32_t* r, uint32_t addr) {
    asm volatile("ldmatrix.sync.aligned.m8n8.x4.shared.b16 {%0,%1,%2,%3}, [%4];"
                 : "=r"(r[0]), "=r"(r[1]), "=r"(r[2]), "=r"(r[3]) : "r"(addr));
}

__device__ __forceinline__ void mma16816(float* c, const uint32_t* a, const uint32_t* b) {
    asm volatile(
        "mma.sync.aligned.m16n8k16.row.col.f32.bf16.bf16.f32 "
        "{%0,%1,%2,%3}, {%4,%5,%6,%7}, {%8,%9}, {%0,%1,%2,%3};"
        : "+f"(c[0]), "+f"(c[1]), "+f"(c[2]), "+f"(c[3])
        : "r"(a[0]), "r"(a[1]), "r"(a[2]), "r"(a[3]), "r"(b[0]), "r"(b[1]));
}

// ---------------- weight prep: src [K,N] fp32 -> [N,K] bf16 hi/lo ----------------
__global__ void wsplit_kernel(const float* __restrict__ src,
                              __nv_bfloat16* __restrict__ dh, __nv_bfloat16* __restrict__ dl,
                              int K, int N) {
    int i = blockIdx.x * 256 + threadIdx.x;
    if (i >= N * K) return;
    int n = i / K, k = i % K;
    __nv_bfloat16 h, l;
    split2(src[k * N + n], h, l);
    dh[i] = h;
    dl[i] = l;
}

// ---------------- bf16 3-split GEMM via mma.sync ----------------
// C[M, NB*128] = act(A[M,K] @ B^T + bias). A fp32 (split on load), B pre-split [N,K] bf16.
// CTA: 128 rows, all NB*128 cols (A tile resident, B reloaded per n-block).
template <int K, int NB, bool RELU>
__global__ __launch_bounds__(256) void gemm_mma(
    const float* __restrict__ A,
    const __nv_bfloat16* __restrict__ Bh, const __nv_bfloat16* __restrict__ Bl,
    const float* __restrict__ bias, float* __restrict__ C)
{
    extern __shared__ char smraw[];
    constexpr int P = K + 8;                 // padded pitch in halves
    __nv_bfloat16* Ah = (__nv_bfloat16*)smraw;
    __nv_bfloat16* Al = Ah + 128 * P;
    __nv_bfloat16* Bsh = Al + 128 * P;
    __nv_bfloat16* Bsl = Bsh + 128 * P;
    const int tid = threadIdx.x, lane = tid & 31, warp = tid >> 5;
    const int m0 = blockIdx.x * 128;
    const int wm = (warp >> 2) * 64, wn = (warp & 3) * 32;
    constexpr int NTOT = NB * 128;

    // ---- load + split A (fp32 -> hi/lo bf16), resident for all n-blocks ----
    constexpr int CH = K / 4;
    for (int i = tid; i < 128 * CH; i += 256) {
        int row = i / CH, c4 = (i % CH) * 4;
        float4 v = *(const float4*)(A + (size_t)(m0 + row) * K + c4);
        __nv_bfloat16 h[4], l[4];
        split2(v.x, h[0], l[0]); split2(v.y, h[1], l[1]);
        split2(v.z, h[2], l[2]); split2(v.w, h[3], l[3]);
        *(uint2*)&Ah[row * P + c4] = *(uint2*)h;
        *(uint2*)&Al[row * P + c4] = *(uint2*)l;
    }

    const uint32_t sA_h = smem_u32(Ah), sA_l = smem_u32(Al);
    const uint32_t sB_h = smem_u32(Bsh), sB_l = smem_u32(Bsl);

    for (int nb = 0; nb < NB; nb++) {
        __syncthreads();   // previous mma done reading Bs (and A visible after first pass)
        constexpr int CH8 = K / 8;
        const uint4* gBh = (const uint4*)(Bh + (size_t)nb * 128 * K);
        const uint4* gBl = (const uint4*)(Bl + (size_t)nb * 128 * K);
        for (int i = tid; i < 128 * CH8; i += 256) {
            int row = i / CH8, c8 = (i % CH8) * 8;
            *(uint4*)&Bsh[row * P + c8] = gBh[i];
            *(uint4*)&Bsl[row * P + c8] = gBl[i];
        }
        __syncthreads();

        float c[4][4][4];
        #pragma unroll
        for (int mt = 0; mt < 4; mt++)
            #pragma unroll
            for (int nt = 0; nt < 4; nt++)
                #pragma unroll
                for (int j = 0; j < 4; j++) c[mt][nt][j] = 0.f;

        // 3 passes: Ah*Bh, Ah*Bl, Al*Bh
        #pragma unroll
        for (int p = 0; p < 3; p++) {
            uint32_t aB = (p == 2) ? sA_l : sA_h;
            uint32_t bB = (p == 1) ? sB_l : sB_h;
            #pragma unroll
            for (int kk = 0; kk < K / 16; kk++) {
                uint32_t a[4][4];
                #pragma unroll
                for (int mt = 0; mt < 4; mt++) {
                    int row = wm + mt * 16 + (lane & 15);
                    uint32_t addr = aB + ((uint32_t)(row * P + kk * 16 + 8 * (lane >> 4)) << 1);
                    ldm4(a[mt], addr);
                }
                uint32_t b[2][4];
                #pragma unroll
                for (int np = 0; np < 2; np++) {
                    int row = wn + np * 16 + ((lane >> 4) << 3) + (lane & 7);
                    uint32_t addr = bB + ((uint32_t)(row * P + kk * 16 + 8 * ((lane >> 3) & 1)) << 1);
                    ldm4(b[np], addr);
                }
                #pragma unroll
                for (int mt = 0; mt < 4; mt++)
                    #pragma unroll
                    for (int nt = 0; nt < 4; nt++) {
                        uint32_t bb[2] = { b[nt >> 1][(nt & 1) * 2], b[nt >> 1][(nt & 1) * 2 + 1] };
                        mma16816(c[mt][nt], a[mt], bb);
                    }
            }
        }

        // ---- epilogue ----
        #pragma unroll
        for (int mt = 0; mt < 4; mt++) {
            int r0 = m0 + wm + mt * 16 + (lane >> 2);
            #pragma unroll
            for (int nt = 0; nt < 4; nt++) {
                int col = nb * 128 + wn + nt * 8 + (lane & 3) * 2;
                float b0 = __ldg(bias + col), b1 = __ldg(bias + col + 1);
                float v0 = c[mt][nt][0] + b0, v1 = c[mt][nt][1] + b1;
                float v2 = c[mt][nt][2] + b0, v3 = c[mt][nt][3] + b1;
                if (RELU) {
                    v0 = fmaxf(v0, 0.f); v1 = fmaxf(v1, 0.f);
                    v2 = fmaxf(v2, 0.f); v3 = fmaxf(v3, 0.f);
                }
                float2 lo = {v0, v1}, hi = {v2, v3};
                *(float2*)(C + (size_t)r0 * NTOT + col) = lo;
                *(float2*)(C + (size_t)(r0 + 8) * NTOT + col) = hi;
            }
        }
    }
}

// ---------------- init ----------------
__global__ void init_kernel() {
    int i = blockIdx.x * 256 + threadIdx.x;
    if (i < NN) { g_m[i] = -INFINITY; g_z[i] = 0.f; }
    if (i < NN * 16) g_agg[i] = 0.f;
    if (i < 64) { g_colsum[i] = 0.f; g_colsumsq[i] = 0.f; }
}

// ---------------- node linears ----------------
__global__ __launch_bounds__(128) void node_kernel(
    const float* __restrict__ node_data, const float* __restrict__ W_input,
    const float* __restrict__ W_query, const float* __restrict__ W_dot)
{
    __shared__ float Wi[64 * 16];
    __shared__ float Wq[16 * 8];
    __shared__ float Wd[64];
    __shared__ float tsh[8][16];
    __shared__ float qsh[8][8];
    int tid = threadIdx.x;
    for (int i = tid; i < 1024; i += 128) Wi[i] = W_input[i];
    if (tid < 128) Wq[tid] = W_query[tid];
    if (tid < 64) Wd[tid] = W_dot[tid];
    __syncthreads();

    int n_loc = tid >> 4, c = tid & 15;
    int n = blockIdx.x * 8 + n_loc;
    float tv = 0.f;
    if (n < NN) {
        const float* nd = node_data + (size_t)n * 64;
        #pragma unroll 8
        for (int i = 0; i < 64; i++) tv += nd[i] * Wi[i * 16 + c];
        tv *= 0.125f;
        g_t[n * 16 + c] = tv;
    }
    tsh[n_loc][c] = tv;
    __syncthreads();

    if (tid < 64) {
        int nl = tid >> 3, b = tid & 7;
        float qv = 0.f;
        #pragma unroll
        for (int a = 0; a < 16; a++) qv += tsh[nl][a] * Wq[a * 8 + b];
        qsh[nl][b] = qv * 0.25f;
    }
    __syncthreads();
    if (tid < 64) {
        int nl = tid >> 3, b = tid & 7;
        int n2 = blockIdx.x * 8 + nl;
        if (n2 < NN) {
            float s = 0.f;
            #pragma unroll
            for (int a = 0; a < 8; a++) s += qsh[nl][a] * Wd[a * 8 + b];
            g_qW[n2 * 8 + b] = s * 0.125f;
        }
    }
}

// ---------------- per-edge bilinear contraction + logits (warp per edge) ----------------
__global__ __launch_bounds__(256) void uv_kernel(
    const int* __restrict__ ei, const float* __restrict__ sh)
{
    int gw = (blockIdx.x * 256 + threadIdx.x) >> 5;
    int lane = threadIdx.x & 31;
    if (gw >= NE) return;
    int e = gw;
    int src = ei[e];
    int dst = ei[NE + e];

    float shl = sh[e * 4 + (lane & 3)];
    float u_lo = g_t[src * 16 + (lane >> 2)] * shl * 0.125f;
    float u_hi = g_t[src * 16 + 8 + (lane >> 2)] * shl * 0.125f;

    const float* wkp = g_WK + (size_t)e * 512;
    float4 ka0 = *(const float4*)(wkp + lane * 8);
    float4 ka1 = *(const float4*)(wkp + lane * 8 + 4);
    float4 kb0 = *(const float4*)(wkp + 256 + lane * 8);
    float4 kb1 = *(const float4*)(wkp + 256 + lane * 8 + 4);
    float kacc[8];
    kacc[0] = u_lo * ka0.x + u_hi * kb0.x;
    kacc[1] = u_lo * ka0.y + u_hi * kb0.y;
    kacc[2] = u_lo * ka0.z + u_hi * kb0.z;
    kacc[3] = u_lo * ka0.w + u_hi * kb0.w;
    kacc[4] = u_lo * ka1.x + u_hi * kb1.x;
    kacc[5] = u_lo * ka1.y + u_hi * kb1.y;
    kacc[6] = u_lo * ka1.z + u_hi * kb1.z;
    kacc[7] = u_lo * ka1.w + u_hi * kb1.w;

    const float* qwp = g_qW + dst * 8;
    float lp = 0.f;
    #pragma unroll
    for (int b = 0; b < 8; b++) lp += kacc[b] * qwp[b];
    #pragma unroll
    for (int off = 16; off; off >>= 1) lp += __shfl_xor_sync(0xffffffffu, lp, off);

    const float* wvp = g_WV + (size_t)e * 1024;
    float vacc[16];
    {
        const float* p = wvp + lane * 16;
        #pragma unroll
        for (int q = 0; q < 4; q++) {
            float4 w = *(const float4*)(p + q * 4);
            vacc[q * 4 + 0] = u_lo * w.x;
            vacc[q * 4 + 1] = u_lo * w.y;
            vacc[q * 4 + 2] = u_lo * w.z;
            vacc[q * 4 + 3] = u_lo * w.w;
        }
        p = wvp + 512 + lane * 16;
        #pragma unroll
        for (int q = 0; q < 4; q++) {
            float4 w = *(const float4*)(p + q * 4);
            vacc[q * 4 + 0] += u_hi * w.x;
            vacc[q * 4 + 1] += u_hi * w.y;
            vacc[q * 4 + 2] += u_hi * w.z;
            vacc[q * 4 + 3] += u_hi * w.w;
        }
    }
    #pragma unroll
    for (int off = 16; off; off >>= 1)
        #pragma unroll
        for (int b = 0; b < 16; b++)
            vacc[b] += __shfl_xor_sync(0xffffffffu, vacc[b], off);

    float vout = 0.f;
    #pragma unroll
    for (int b = 0; b < 16; b++) vout = (lane == b) ? vacc[b] : vout;
    if (lane < 16) g_vbuf[(size_t)e * 16 + lane] = vout;
    if (lane == 0) {
        g_logit[e] = lp;
        atomicMaxF(&g_m[dst], lp);
    }
}

// ---------------- softmax numerator + segment sums ----------------
__global__ void attn_agg_kernel(const int* __restrict__ ei)
{
    int e = blockIdx.x * 256 + threadIdx.x;
    if (e >= NE) return;
    int dst = ei[NE + e];
    float p = expf(g_logit[e] - g_m[dst]);
    atomicAdd(&g_z[dst], p);
    const float* v = g_vbuf + (size_t)e * 16;
    float* agg = g_agg + dst * 16;
    #pragma unroll
    for (int c = 0; c < 16; c++) atomicAdd(&agg[c], p * v[c]);
}

// ---------------- output linear + residual + BN stats ----------------
__global__ __launch_bounds__(256) void out_stats_kernel(
    const float* __restrict__ node_data, const float* __restrict__ W_output)
{
    __shared__ float Wsh[16 * 64];
    __shared__ float red[256];
    int tid = threadIdx.x;
    for (int i = tid; i < 1024; i += 256) Wsh[i] = W_output[i];
    __syncthreads();

    int c = tid & 63;
    int r = tid >> 6;
    int n0 = blockIdx.x * 64;
    float lsum = 0.f, lsq = 0.f;
    for (int i = 0; i < 16; i++) {
        int n = n0 + r + i * 4;
        if (n < NN) {
            float zz = g_z[n];
            float inv = zz > 0.f ? 0.25f / zz : 0.f;
            float o = 0.f;
            const float* agg = g_agg + n * 16;
            #pragma unroll
            for (int j = 0; j < 16; j++) o += agg[j] * Wsh[j * 64 + c];
            o = o * inv + node_data[(size_t)n * 64 + c];
            g_outpre[(size_t)n * 64 + c] = o;
            lsum += o;
            lsq += o * o;
        }
    }
    red[tid] = lsum;
    __syncthreads();
    if (r == 0) atomicAdd(&g_colsum[c], red[c] + red[64 + c] + red[128 + c] + red[192 + c]);
    __syncthreads();
    red[tid] = lsq;
    __syncthreads();
    if (r == 0) atomicAdd(&g_colsumsq[c], red[c] + red[64 + c] + red[128 + c] + red[192 + c]);
}

// ---------------- batchnorm finalize ----------------
__global__ void bn_kernel(const float* __restrict__ bnw, const float* __restrict__ bnb,
                          float* __restrict__ out)
{
    int i = blockIdx.x * 256 + threadIdx.x;
    if (i >= NN * 64) return;
    int c = i & 63;
    const float invN = 1.f / NN;
    float mean = g_colsum[c] * invN;
    float var = g_colsumsq[c] * invN - mean * mean;
    out[i] = (g_outpre[i] - mean) * rsqrtf(var + 1e-5f) * bnw[c] + bnb[c];
}

// ---------------- launch ----------------
extern "C" void kernel_launch(void* const* d_in, const int* in_sizes, int n_in,
                              void* d_out, int out_size)
{
    const float* node_data = (const float*)d_in[0];
    const int*   edge_index = (const int*)d_in[1];
    const float* edge_data = (const float*)d_in[2];
    const float* edge_sh   = (const float*)d_in[3];
    const float* W_input = (const float*)d_in[4];
    const float* W_query = (const float*)d_in[5];
    const float* W_dot   = (const float*)d_in[6];
    const float* W_output = (const float*)d_in[7];
    const float* Wk1 = (const float*)d_in[8];
    const float* bk1 = (const float*)d_in[9];
    const float* Wk2 = (const float*)d_in[10];
    const float* bk2 = (const float*)d_in[11];
    const float* Wk3 = (const float*)d_in[12];
    const float* bk3 = (const float*)d_in[13];
    const float* Wv1 = (const float*)d_in[14];
    const float* bv1 = (const float*)d_in[15];
    const float* Wv2 = (const float*)d_in[16];
    const float* bv2 = (const float*)d_in[17];
    const float* Wv3 = (const float*)d_in[18];
    const float* bv3 = (const float*)d_in[19];
    const float* bn_weight = (const float*)d_in[20];
    const float* bn_bias   = (const float*)d_in[21];
    float* out = (float*)d_out;

    void *p1k, *p2k, *p1v, *p2v, *pWK, *pWV;
    void *pw1kh, *pw1kl, *pw1vh, *pw1vl, *pw2kh, *pw2kl, *pw2vh, *pw2vl;
    void *pw3kh, *pw3kl, *pw3vh, *pw3vl;
    cudaGetSymbolAddress(&p1k, g_h1k); cudaGetSymbolAddress(&p2k, g_h2k);
    cudaGetSymbolAddress(&p1v, g_h1v); cudaGetSymbolAddress(&p2v, g_h2v);
    cudaGetSymbolAddress(&pWK, g_WK);  cudaGetSymbolAddress(&pWV, g_WV);
    cudaGetSymbolAddress(&pw1kh, g_w1k_h); cudaGetSymbolAddress(&pw1kl, g_w1k_l);
    cudaGetSymbolAddress(&pw1vh, g_w1v_h); cudaGetSymbolAddress(&pw1vl, g_w1v_l);
    cudaGetSymbolAddress(&pw2kh, g_w2k_h); cudaGetSymbolAddress(&pw2kl, g_w2k_l);
    cudaGetSymbolAddress(&pw2vh, g_w2v_h); cudaGetSymbolAddress(&pw2vl, g_w2v_l);
    cudaGetSymbolAddress(&pw3kh, g_w3k_h); cudaGetSymbolAddress(&pw3kl, g_w3k_l);
    cudaGetSymbolAddress(&pw3vh, g_w3v_h); cudaGetSymbolAddress(&pw3vl, g_w3v_l);

    const int SM32 = 4 * 128 * (32 + 8) * 2;    // 40960
    const int SM128 = 4 * 128 * (128 + 8) * 2;  // 139264
    cudaFuncSetAttribute(gemm_mma<32, 1, true>, cudaFuncAttributeMaxDynamicSharedMemorySize, SM32);
    cudaFuncSetAttribute(gemm_mma<128, 1, true>, cudaFuncAttributeMaxDynamicSharedMemorySize, SM128);
    cudaFuncSetAttribute(gemm_mma<128, 4, false>, cudaFuncAttributeMaxDynamicSharedMemorySize, SM128);
    cudaFuncSetAttribute(gemm_mma<128, 8, false>, cudaFuncAttributeMaxDynamicSharedMemorySize, SM128);

    // prep
    init_kernel<<<(NE + 255) / 256, 256>>>();
    wsplit_kernel<<<(128 * 32 + 255) / 256, 256>>>(Wk1, (__nv_bfloat16*)pw1kh, (__nv_bfloat16*)pw1kl, 32, 128);
    wsplit_kernel<<<(128 * 32 + 255) / 256, 256>>>(Wv1, (__nv_bfloat16*)pw1vh, (__nv_bfloat16*)pw1vl, 32, 128);
    wsplit_kernel<<<(128 * 128 + 255) / 256, 256>>>(Wk2, (__nv_bfloat16*)pw2kh, (__nv_bfloat16*)pw2kl, 128, 128);
    wsplit_kernel<<<(128 * 128 + 255) / 256, 256>>>(Wv2, (__nv_bfloat16*)pw2vh, (__nv_bfloat16*)pw2vl, 128, 128);
    wsplit_kernel<<<(512 * 128 + 255) / 256, 256>>>(Wk3, (__nv_bfloat16*)pw3kh, (__nv_bfloat16*)pw3kl, 128, 512);
    wsplit_kernel<<<(1024 * 128 + 255) / 256, 256>>>(Wv3, (__nv_bfloat16*)pw3vh, (__nv_bfloat16*)pw3vl, 128, 1024);
    node_kernel<<<(NN + 7) / 8, 128>>>(node_data, W_input, W_query, W_dot);

    // GEMM chain (mma.sync tensor cores, 3-pass bf16 split)
    gemm_mma<32, 1, true><<<NE / 128, 256, SM32>>>(
        edge_data, (const __nv_bfloat16*)pw1kh, (const __nv_bfloat16*)pw1kl, bk1, (float*)p1k);
    gemm_mma<32, 1, true><<<NE / 128, 256, SM32>>>(
        edge_data, (const __nv_bfloat16*)pw1vh, (const __nv_bfloat16*)pw1vl, bv1, (float*)p1v);
    gemm_mma<128, 1, true><<<NE / 128, 256, SM128>>>(
        (const float*)p1k, (const __nv_bfloat16*)pw2kh, (const __nv_bfloat16*)pw2kl, bk2, (float*)p2k);
    gemm_mma<128, 1, true><<<NE / 128, 256, SM128>>>(
        (const float*)p1v, (const __nv_bfloat16*)pw2vh, (const __nv_bfloat16*)pw2vl, bv2, (float*)p2v);
    gemm_mma<128, 4, false><<<NE / 128, 256, SM128>>>(
        (const float*)p2k, (const __nv_bfloat16*)pw3kh, (const __nv_bfloat16*)pw3kl, bk3, (float*)pWK);
    gemm_mma<128, 8, false><<<NE / 128, 256, SM128>>>(
        (const float*)p2v, (const __nv_bfloat16*)pw3vh, (const __nv_bfloat16*)pw3vl, bv3, (float*)pWV);

    // tail
    uv_kernel<<<NE / 8, 256>>>(edge_index, edge_sh);
    attn_agg_kernel<<<(NE + 255) / 256, 256>>>(edge_index);
    out_stats_kernel<<<(NN + 63) / 64, 256>>>(node_data, W_output);
    bn_kernel<<<(NN * 64 + 255) / 256, 256>>>(bn_weight, bn_bias, out);
}

// round 7
// speedup vs baseline: 1.8030x; 1.1587x over previous
#include <cuda_runtime.h>
#include <cuda_bf16.h>
#include <stdint.h>
#include <math.h>

#define NN 10000
#define NE 160000

// ---------------- device scratch (static, allocation-free) ----------------
__device__ float g_t[NN * 16];
__device__ float g_qW[NN * 8];
__device__ float g_h1k[(size_t)NE * 128];
__device__ float g_h2k[(size_t)NE * 128];
__device__ float g_h1v[(size_t)NE * 128];
__device__ float g_h2v[(size_t)NE * 128];
// transposed, split weights [N, K] bf16
__device__ __nv_bfloat16 g_w1k_h[128 * 32], g_w1k_l[128 * 32];
__device__ __nv_bfloat16 g_w1v_h[128 * 32], g_w1v_l[128 * 32];
__device__ __nv_bfloat16 g_w2k_h[128 * 128], g_w2k_l[128 * 128];
__device__ __nv_bfloat16 g_w2v_h[128 * 128], g_w2v_l[128 * 128];
__device__ __nv_bfloat16 g_w3k_h[512 * 128], g_w3k_l[512 * 128];
__device__ __nv_bfloat16 g_w3v_h[1024 * 128], g_w3v_l[1024 * 128];
// fp32 tail
__device__ float g_vbuf[(size_t)NE * 16];
__device__ float g_logit[NE];
__device__ float g_m[NN];
__device__ float g_z[NN];
__device__ float g_agg[NN * 16];
__device__ float g_colsum[64];
__device__ float g_colsumsq[64];
__device__ float g_outpre[NN * 64];

// ---------------- helpers ----------------
__device__ __forceinline__ void atomicMaxF(float* addr, float v) {
    if (v >= 0.f)
        atomicMax((int*)addr, __float_as_int(v));
    else
        atomicMin((unsigned int*)addr, __float_as_uint(v));
}

__device__ __forceinline__ uint32_t smem_u32(const void* p) {
    uint32_t a;
    asm("{ .reg .u64 t; cvta.to.shared.u64 t, %1; cvt.u32.u64 %0, t; }" : "=r"(a) : "l"(p));
    return a;
}

__device__ __forceinline__ void split2(float x, __nv_bfloat16& h, __nv_bfloat16& l) {
    h = __float2bfloat16(x);
    l = __float2bfloat16(x - __bfloat162float(h));
}

__device__ __forceinline__ void ldm4(uint32_t* r, uint32_t addr) {
    asm volatile("ldmatrix.sync.aligned.m8n8.x4.shared.b16 {%0,%1,%2,%3}, [%4];"
                 : "=r"(r[0]), "=r"(r[1]), "=r"(r[2]), "=r"(r[3]) : "r"(addr));
}

__device__ __forceinline__ void mma16816(float* c, const uint32_t* a, const uint32_t* b) {
    asm volatile(
        "mma.sync.aligned.m16n8k16.row.col.f32.bf16.bf16.f32 "
        "{%0,%1,%2,%3}, {%4,%5,%6,%7}, {%8,%9}, {%0,%1,%2,%3};"
        : "+f"(c[0]), "+f"(c[1]), "+f"(c[2]), "+f"(c[3])
        : "r"(a[0]), "r"(a[1]), "r"(a[2]), "r"(a[3]), "r"(b[0]), "r"(b[1]));
}

// ---------------- weight prep: all 6 weights in one kernel ----------------
__device__ __forceinline__ void wsplit_one(const float* src, __nv_bfloat16* dh,
                                           __nv_bfloat16* dl, int K, int N, int i) {
    int n = i / K, k = i % K;
    __nv_bfloat16 h, l;
    split2(src[k * N + n], h, l);
    dh[i] = h;
    dl[i] = l;
}

__global__ void wsplit_all(const float* __restrict__ Wk1, const float* __restrict__ Wv1,
                           const float* __restrict__ Wk2, const float* __restrict__ Wv2,
                           const float* __restrict__ Wk3, const float* __restrict__ Wv3)
{
    int i = blockIdx.x * 256 + threadIdx.x;
    // segments: 4096, 4096, 16384, 16384, 65536, 131072 (total 237568)
    if (i < 4096) { wsplit_one(Wk1, g_w1k_h, g_w1k_l, 32, 128, i); return; }
    i -= 4096;
    if (i < 4096) { wsplit_one(Wv1, g_w1v_h, g_w1v_l, 32, 128, i); return; }
    i -= 4096;
    if (i < 16384) { wsplit_one(Wk2, g_w2k_h, g_w2k_l, 128, 128, i); return; }
    i -= 16384;
    if (i < 16384) { wsplit_one(Wv2, g_w2v_h, g_w2v_l, 128, 128, i); return; }
    i -= 16384;
    if (i < 65536) { wsplit_one(Wk3, g_w3k_h, g_w3k_l, 128, 512, i); return; }
    i -= 65536;
    if (i < 131072) { wsplit_one(Wv3, g_w3v_h, g_w3v_l, 128, 1024, i); }
}

// ---------------- bf16 3-split GEMM via mma.sync (layers 1-2) ----------------
template <int K, bool RELU>
__global__ __launch_bounds__(256) void gemm_mma(
    const float* __restrict__ A,
    const __nv_bfloat16* __restrict__ Bh, const __nv_bfloat16* __restrict__ Bl,
    const float* __restrict__ bias, float* __restrict__ C)
{
    extern __shared__ char smraw[];
    constexpr int P = K + 8;
    __nv_bfloat16* Ah = (__nv_bfloat16*)smraw;
    __nv_bfloat16* Al = Ah + 128 * P;
    __nv_bfloat16* Bsh = Al + 128 * P;
    __nv_bfloat16* Bsl = Bsh + 128 * P;
    const int tid = threadIdx.x, lane = tid & 31, warp = tid >> 5;
    const int m0 = blockIdx.x * 128;
    const int wm = (warp >> 2) * 64, wn = (warp & 3) * 32;

    constexpr int CH = K / 4;
    for (int i = tid; i < 128 * CH; i += 256) {
        int row = i / CH, c4 = (i % CH) * 4;
        float4 v = *(const float4*)(A + (size_t)(m0 + row) * K + c4);
        __nv_bfloat16 h[4], l[4];
        split2(v.x, h[0], l[0]); split2(v.y, h[1], l[1]);
        split2(v.z, h[2], l[2]); split2(v.w, h[3], l[3]);
        *(uint2*)&Ah[row * P + c4] = *(uint2*)h;
        *(uint2*)&Al[row * P + c4] = *(uint2*)l;
    }
    constexpr int CH8 = K / 8;
    const uint4* gBh = (const uint4*)Bh;
    const uint4* gBl = (const uint4*)Bl;
    for (int i = tid; i < 128 * CH8; i += 256) {
        int row = i / CH8, c8 = (i % CH8) * 8;
        *(uint4*)&Bsh[row * P + c8] = gBh[i];
        *(uint4*)&Bsl[row * P + c8] = gBl[i];
    }
    __syncthreads();

    const uint32_t sA_h = smem_u32(Ah), sA_l = smem_u32(Al);
    const uint32_t sB_h = smem_u32(Bsh), sB_l = smem_u32(Bsl);

    float c[4][4][4];
    #pragma unroll
    for (int mt = 0; mt < 4; mt++)
        #pragma unroll
        for (int nt = 0; nt < 4; nt++)
            #pragma unroll
            for (int j = 0; j < 4; j++) c[mt][nt][j] = 0.f;

    #pragma unroll
    for (int p = 0; p < 3; p++) {
        uint32_t aB = (p == 2) ? sA_l : sA_h;
        uint32_t bB = (p == 1) ? sB_l : sB_h;
        #pragma unroll
        for (int kk = 0; kk < K / 16; kk++) {
            uint32_t a[4][4];
            #pragma unroll
            for (int mt = 0; mt < 4; mt++) {
                int row = wm + mt * 16 + (lane & 15);
                uint32_t addr = aB + ((uint32_t)(row * P + kk * 16 + 8 * (lane >> 4)) << 1);
                ldm4(a[mt], addr);
            }
            uint32_t b[2][4];
            #pragma unroll
            for (int np = 0; np < 2; np++) {
                int row = wn + np * 16 + ((lane >> 4) << 3) + (lane & 7);
                uint32_t addr = bB + ((uint32_t)(row * P + kk * 16 + 8 * ((lane >> 3) & 1)) << 1);
                ldm4(b[np], addr);
            }
            #pragma unroll
            for (int mt = 0; mt < 4; mt++)
                #pragma unroll
                for (int nt = 0; nt < 4; nt++) {
                    uint32_t bb[2] = { b[nt >> 1][(nt & 1) * 2], b[nt >> 1][(nt & 1) * 2 + 1] };
                    mma16816(c[mt][nt], a[mt], bb);
                }
        }
    }

    #pragma unroll
    for (int mt = 0; mt < 4; mt++) {
        int r0 = m0 + wm + mt * 16 + (lane >> 2);
        #pragma unroll
        for (int nt = 0; nt < 4; nt++) {
            int col = wn + nt * 8 + (lane & 3) * 2;
            float b0 = __ldg(bias + col), b1 = __ldg(bias + col + 1);
            float v0 = c[mt][nt][0] + b0, v1 = c[mt][nt][1] + b1;
            float v2 = c[mt][nt][2] + b0, v3 = c[mt][nt][3] + b1;
            if (RELU) {
                v0 = fmaxf(v0, 0.f); v1 = fmaxf(v1, 0.f);
                v2 = fmaxf(v2, 0.f); v3 = fmaxf(v3, 0.f);
            }
            float2 lo = {v0, v1}, hi = {v2, v3};
            *(float2*)(C + (size_t)r0 * 128 + col) = lo;
            *(float2*)(C + (size_t)(r0 + 8) * 128 + col) = hi;
        }
    }
}

// ---------------- layer-3 GEMM fused with per-edge contraction ----------------
// NOUT=8: K-path (logit); NOUT=16: V-path (vbuf). K=128.
// contraction: out[e,ob] = sum_as u[e,as] * (h2[e,:]@W3[:,as*NOUT+ob] + b3[as*NOUT+ob])
template <int NOUT, int NB>
__global__ __launch_bounds__(256) void gemm3_fused(
    const float* __restrict__ A,
    const __nv_bfloat16* __restrict__ Bh, const __nv_bfloat16* __restrict__ Bl,
    const float* __restrict__ bias,
    const int* __restrict__ ei, const float* __restrict__ sh)
{
    constexpr int K = 128, P = 136, NTOT = NB * 128;
    constexpr int NSLOT = (NOUT == 16) ? 4 : 2;
    constexpr int PP = NOUT + 1;            // padded partial pitch
    extern __shared__ char smraw[];
    __nv_bfloat16* Ah = (__nv_bfloat16*)smraw;
    __nv_bfloat16* Al = Ah + 128 * P;
    __nv_bfloat16* Bsh = Al + 128 * P;
    __nv_bfloat16* Bsl = Bsh + 128 * P;
    float* u_s = (float*)(smraw + 4 * 128 * P * 2);       // [128][65]
    float* part = u_s + 128 * 65;                          // [4][128][PP]
    float* bs = (float*)(smraw + 2 * 128 * P * 2);         // overlay on Bs (used post-mma)

    const int tid = threadIdx.x, lane = tid & 31, warp = tid >> 5;
    const int m0 = blockIdx.x * 128;
    const int wm = (warp >> 2) * 64, wn = (warp & 3) * 32;

    // A load + split
    for (int i = tid; i < 128 * 32; i += 256) {
        int row = i >> 5, c4 = (i & 31) * 4;
        float4 v = *(const float4*)(A + (size_t)(m0 + row) * K + c4);
        __nv_bfloat16 h[4], l[4];
        split2(v.x, h[0], l[0]); split2(v.y, h[1], l[1]);
        split2(v.z, h[2], l[2]); split2(v.w, h[3], l[3]);
        *(uint2*)&Ah[row * P + c4] = *(uint2*)h;
        *(uint2*)&Al[row * P + c4] = *(uint2*)l;
    }
    // u = t[src] (x) sh / 8
    for (int i = tid; i < 128 * 64; i += 256) {
        int row = i >> 6, as = i & 63;
        int e = m0 + row;
        int src = ei[e];
        u_s[row * 65 + as] = g_t[src * 16 + (as >> 2)] * sh[e * 4 + (as & 3)] * 0.125f;
    }

    const uint32_t sA_h = smem_u32(Ah), sA_l = smem_u32(Al);
    const uint32_t sB_h = smem_u32(Bsh), sB_l = smem_u32(Bsl);

    float loc[8][NSLOT];
    #pragma unroll
    for (int s = 0; s < 8; s++)
        #pragma unroll
        for (int j = 0; j < NSLOT; j++) loc[s][j] = 0.f;

    for (int nb = 0; nb < NB; nb++) {
        __syncthreads();   // A/u visible (nb=0); prev mma done reading Bs (nb>0)
        const uint4* gBh = (const uint4*)(Bh + (size_t)nb * 128 * K);
        const uint4* gBl = (const uint4*)(Bl + (size_t)nb * 128 * K);
        for (int i = tid; i < 128 * 16; i += 256) {
            int row = i >> 4, c8 = (i & 15) * 8;
            *(uint4*)&Bsh[row * P + c8] = gBh[i];
            *(uint4*)&Bsl[row * P + c8] = gBl[i];
        }
        __syncthreads();

        float c[4][4][4];
        #pragma unroll
        for (int mt = 0; mt < 4; mt++)
            #pragma unroll
            for (int nt = 0; nt < 4; nt++)
                #pragma unroll
                for (int j = 0; j < 4; j++) c[mt][nt][j] = 0.f;

        #pragma unroll
        for (int p = 0; p < 3; p++) {
            uint32_t aB = (p == 2) ? sA_l : sA_h;
            uint32_t bB = (p == 1) ? sB_l : sB_h;
            #pragma unroll
            for (int kk = 0; kk < K / 16; kk++) {
                uint32_t a[4][4];
                #pragma unroll
                for (int mt = 0; mt < 4; mt++) {
                    int row = wm + mt * 16 + (lane & 15);
                    uint32_t addr = aB + ((uint32_t)(row * P + kk * 16 + 8 * (lane >> 4)) << 1);
                    ldm4(a[mt], addr);
                }
                uint32_t b[2][4];
                #pragma unroll
                for (int np = 0; np < 2; np++) {
                    int row = wn + np * 16 + ((lane >> 4) << 3) + (lane & 7);
                    uint32_t addr = bB + ((uint32_t)(row * P + kk * 16 + 8 * ((lane >> 3) & 1)) << 1);
                    ldm4(b[np], addr);
                }
                #pragma unroll
                for (int mt = 0; mt < 4; mt++)
                    #pragma unroll
                    for (int nt = 0; nt < 4; nt++) {
                        uint32_t bb[2] = { b[nt >> 1][(nt & 1) * 2], b[nt >> 1][(nt & 1) * 2 + 1] };
                        mma16816(c[mt][nt], a[mt], bb);
                    }
            }
        }

        // fold fragments into contraction accumulators
        #pragma unroll
        for (int mt = 0; mt < 4; mt++) {
            int r = wm + mt * 16 + (lane >> 2);
            #pragma unroll
            for (int nt = 0; nt < 4; nt++) {
                int colb = nb * 128 + wn + nt * 8;   // (lane&3)*2 doesn't cross as-block
                int as = (NOUT == 16) ? (colb >> 4) : (colb >> 3);
                int obi = (NOUT == 16) ? ((nt & 1) * 2) : 0;
                float ur = u_s[r * 65 + as];
                float ur8 = u_s[(r + 8) * 65 + as];
                loc[mt * 2][obi]     += c[mt][nt][0] * ur;
                loc[mt * 2][obi + 1] += c[mt][nt][1] * ur;
                loc[mt * 2 + 1][obi]     += c[mt][nt][2] * ur8;
                loc[mt * 2 + 1][obi + 1] += c[mt][nt][3] * ur8;
            }
        }
    }

    // per-warp partials -> smem
    {
        int wi = warp & 3;
        #pragma unroll
        for (int s = 0; s < 8; s++) {
            int row = wm + (s >> 1) * 16 + (s & 1) * 8 + (lane >> 2);
            #pragma unroll
            for (int j = 0; j < NSLOT; j++) {
                int ob = (lane & 3) * 2 + (j & 1) + (j >> 1) * 8;
                part[(wi * 128 + row) * PP + ob] = loc[s][j];
            }
        }
    }
    // stage bias (Bs region is free now)
    for (int i = tid; i < NTOT; i += 256) bs[i] = bias[i];
    __syncthreads();

    if (NOUT == 16) {
        for (int idx = tid; idx < 128 * 16; idx += 256) {
            int row = idx >> 4, ob = idx & 15;
            float s = part[row * PP + ob] + part[(128 + row) * PP + ob]
                    + part[(256 + row) * PP + ob] + part[(384 + row) * PP + ob];
            float bt = 0.f;
            #pragma unroll
            for (int as = 0; as < 64; as++) bt = fmaf(u_s[row * 65 + as], bs[as * 16 + ob], bt);
            g_vbuf[(size_t)(m0 + row) * 16 + ob] = s + bt;
        }
    } else {
        for (int idx = tid; idx < 128 * 8; idx += 256) {
            int row = idx >> 3, b = idx & 7;
            float s = part[row * PP + b] + part[(128 + row) * PP + b]
                    + part[(256 + row) * PP + b] + part[(384 + row) * PP + b];
            float bt = 0.f;
            #pragma unroll
            for (int as = 0; as < 64; as++) bt = fmaf(u_s[row * 65 + as], bs[as * 8 + b], bt);
            part[row * PP + b] = s + bt;   // same-thread slot rewrite, safe
        }
        __syncthreads();
        if (tid < 128) {
            int e = m0 + tid;
            int dst = ei[NE + e];
            float lp = 0.f;
            #pragma unroll
            for (int b = 0; b < 8; b++) lp += part[tid * PP + b] * g_qW[dst * 8 + b];
            g_logit[e] = lp;
            atomicMaxF(&g_m[dst], lp);
        }
    }
}

// ---------------- init ----------------
__global__ void init_kernel() {
    int i = blockIdx.x * 256 + threadIdx.x;
    if (i < NN) { g_m[i] = -INFINITY; g_z[i] = 0.f; }
    if (i < NN * 16) g_agg[i] = 0.f;
    if (i < 64) { g_colsum[i] = 0.f; g_colsumsq[i] = 0.f; }
}

// ---------------- node linears ----------------
__global__ __launch_bounds__(128) void node_kernel(
    const float* __restrict__ node_data, const float* __restrict__ W_input,
    const float* __restrict__ W_query, const float* __restrict__ W_dot)
{
    __shared__ float Wi[64 * 16];
    __shared__ float Wq[16 * 8];
    __shared__ float Wd[64];
    __shared__ float tsh[8][16];
    __shared__ float qsh[8][8];
    int tid = threadIdx.x;
    for (int i = tid; i < 1024; i += 128) Wi[i] = W_input[i];
    if (tid < 128) Wq[tid] = W_query[tid];
    if (tid < 64) Wd[tid] = W_dot[tid];
    __syncthreads();

    int n_loc = tid >> 4, c = tid & 15;
    int n = blockIdx.x * 8 + n_loc;
    float tv = 0.f;
    if (n < NN) {
        const float* nd = node_data + (size_t)n * 64;
        #pragma unroll 8
        for (int i = 0; i < 64; i++) tv += nd[i] * Wi[i * 16 + c];
        tv *= 0.125f;
        g_t[n * 16 + c] = tv;
    }
    tsh[n_loc][c] = tv;
    __syncthreads();

    if (tid < 64) {
        int nl = tid >> 3, b = tid & 7;
        float qv = 0.f;
        #pragma unroll
        for (int a = 0; a < 16; a++) qv += tsh[nl][a] * Wq[a * 8 + b];
        qsh[nl][b] = qv * 0.25f;
    }
    __syncthreads();
    if (tid < 64) {
        int nl = tid >> 3, b = tid & 7;
        int n2 = blockIdx.x * 8 + nl;
        if (n2 < NN) {
            float s = 0.f;
            #pragma unroll
            for (int a = 0; a < 8; a++) s += qsh[nl][a] * Wd[a * 8 + b];
            g_qW[n2 * 8 + b] = s * 0.125f;
        }
    }
}

// ---------------- softmax numerator + segment sums ----------------
__global__ void attn_agg_kernel(const int* __restrict__ ei)
{
    int e = blockIdx.x * 256 + threadIdx.x;
    if (e >= NE) return;
    int dst = ei[NE + e];
    float p = expf(g_logit[e] - g_m[dst]);
    atomicAdd(&g_z[dst], p);
    const float* v = g_vbuf + (size_t)e * 16;
    float* agg = g_agg + dst * 16;
    #pragma unroll
    for (int c = 0; c < 16; c++) atomicAdd(&agg[c], p * v[c]);
}

// ---------------- output linear + residual + BN stats ----------------
__global__ __launch_bounds__(256) void out_stats_kernel(
    const float* __restrict__ node_data, const float* __restrict__ W_output)
{
    __shared__ float Wsh[16 * 64];
    __shared__ float red[256];
    int tid = threadIdx.x;
    for (int i = tid; i < 1024; i += 256) Wsh[i] = W_output[i];
    __syncthreads();

    int c = tid & 63;
    int r = tid >> 6;
    int n0 = blockIdx.x * 64;
    float lsum = 0.f, lsq = 0.f;
    for (int i = 0; i < 16; i++) {
        int n = n0 + r + i * 4;
        if (n < NN) {
            float zz = g_z[n];
            float inv = zz > 0.f ? 0.25f / zz : 0.f;
            float o = 0.f;
            const float* agg = g_agg + n * 16;
            #pragma unroll
            for (int j = 0; j < 16; j++) o += agg[j] * Wsh[j * 64 + c];
            o = o * inv + node_data[(size_t)n * 64 + c];
            g_outpre[(size_t)n * 64 + c] = o;
            lsum += o;
            lsq += o * o;
        }
    }
    red[tid] = lsum;
    __syncthreads();
    if (r == 0) atomicAdd(&g_colsum[c], red[c] + red[64 + c] + red[128 + c] + red[192 + c]);
    __syncthreads();
    red[tid] = lsq;
    __syncthreads();
    if (r == 0) atomicAdd(&g_colsumsq[c], red[c] + red[64 + c] + red[128 + c] + red[192 + c]);
}

// ---------------- batchnorm finalize ----------------
__global__ void bn_kernel(const float* __restrict__ bnw, const float* __restrict__ bnb,
                          float* __restrict__ out)
{
    int i = blockIdx.x * 256 + threadIdx.x;
    if (i >= NN * 64) return;
    int c = i & 63;
    const float invN = 1.f / NN;
    float mean = g_colsum[c] * invN;
    float var = g_colsumsq[c] * invN - mean * mean;
    out[i] = (g_outpre[i] - mean) * rsqrtf(var + 1e-5f) * bnw[c] + bnb[c];
}

// ---------------- launch ----------------
extern "C" void kernel_launch(void* const* d_in, const int* in_sizes, int n_in,
                              void* d_out, int out_size)
{
    const float* node_data = (const float*)d_in[0];
    const int*   edge_index = (const int*)d_in[1];
    const float* edge_data = (const float*)d_in[2];
    const float* edge_sh   = (const float*)d_in[3];
    const float* W_input = (const float*)d_in[4];
    const float* W_query = (const float*)d_in[5];
    const float* W_dot   = (const float*)d_in[6];
    const float* W_output = (const float*)d_in[7];
    const float* Wk1 = (const float*)d_in[8];
    const float* bk1 = (const float*)d_in[9];
    const float* Wk2 = (const float*)d_in[10];
    const float* bk2 = (const float*)d_in[11];
    const float* Wk3 = (const float*)d_in[12];
    const float* bk3 = (const float*)d_in[13];
    const float* Wv1 = (const float*)d_in[14];
    const float* bv1 = (const float*)d_in[15];
    const float* Wv2 = (const float*)d_in[16];
    const float* bv2 = (const float*)d_in[17];
    const float* Wv3 = (const float*)d_in[18];
    const float* bv3 = (const float*)d_in[19];
    const float* bn_weight = (const float*)d_in[20];
    const float* bn_bias   = (const float*)d_in[21];
    float* out = (float*)d_out;

    void *p1k, *p2k, *p1v, *p2v;
    void *pw1kh, *pw1kl, *pw1vh, *pw1vl, *pw2kh, *pw2kl, *pw2vh, *pw2vl;
    void *pw3kh, *pw3kl, *pw3vh, *pw3vl;
    cudaGetSymbolAddress(&p1k, g_h1k); cudaGetSymbolAddress(&p2k, g_h2k);
    cudaGetSymbolAddress(&p1v, g_h1v); cudaGetSymbolAddress(&p2v, g_h2v);
    cudaGetSymbolAddress(&pw1kh, g_w1k_h); cudaGetSymbolAddress(&pw1kl, g_w1k_l);
    cudaGetSymbolAddress(&pw1vh, g_w1v_h); cudaGetSymbolAddress(&pw1vl, g_w1v_l);
    cudaGetSymbolAddress(&pw2kh, g_w2k_h); cudaGetSymbolAddress(&pw2kl, g_w2k_l);
    cudaGetSymbolAddress(&pw2vh, g_w2v_h); cudaGetSymbolAddress(&pw2vl, g_w2v_l);
    cudaGetSymbolAddress(&pw3kh, g_w3k_h); cudaGetSymbolAddress(&pw3kl, g_w3k_l);
    cudaGetSymbolAddress(&pw3vh, g_w3v_h); cudaGetSymbolAddress(&pw3vl, g_w3v_l);

    const int SM32 = 4 * 128 * (32 + 8) * 2;       // 40960
    const int SM128 = 4 * 128 * (128 + 8) * 2;     // 139264
    const int SMF_V = SM128 + 128 * 65 * 4 + 4 * 128 * 17 * 4;  // 207360
    const int SMF_K = SM128 + 128 * 65 * 4 + 4 * 128 * 9 * 4;   // 190976
    cudaFuncSetAttribute(gemm_mma<32, true>, cudaFuncAttributeMaxDynamicSharedMemorySize, SM32);
    cudaFuncSetAttribute(gemm_mma<128, true>, cudaFuncAttributeMaxDynamicSharedMemorySize, SM128);
    cudaFuncSetAttribute(gemm3_fused<16, 8>, cudaFuncAttributeMaxDynamicSharedMemorySize, SMF_V);
    cudaFuncSetAttribute(gemm3_fused<8, 4>, cudaFuncAttributeMaxDynamicSharedMemorySize, SMF_K);

    // launch order chosen so ncu (-s 5 -c 1) captures the fused V GEMM
    init_kernel<<<(NE + 255) / 256, 256>>>();                                   // 0
    wsplit_all<<<(237568 + 255) / 256, 256>>>(Wk1, Wv1, Wk2, Wv2, Wk3, Wv3);    // 1
    node_kernel<<<(NN + 7) / 8, 128>>>(node_data, W_input, W_query, W_dot);     // 2
    gemm_mma<32, true><<<NE / 128, 256, SM32>>>(                                // 3
        edge_data, (const __nv_bfloat16*)pw1vh, (const __nv_bfloat16*)pw1vl, bv1, (float*)p1v);
    gemm_mma<128, true><<<NE / 128, 256, SM128>>>(                              // 4
        (const float*)p1v, (const __nv_bfloat16*)pw2vh, (const __nv_bfloat16*)pw2vl, bv2, (float*)p2v);
    gemm3_fused<16, 8><<<NE / 128, 256, SMF_V>>>(                               // 5 <- ncu
        (const float*)p2v, (const __nv_bfloat16*)pw3vh, (const __nv_bfloat16*)pw3vl,
        bv3, edge_index, edge_sh);
    gemm_mma<32, true><<<NE / 128, 256, SM32>>>(                                // 6
        edge_data, (const __nv_bfloat16*)pw1kh, (const __nv_bfloat16*)pw1kl, bk1, (float*)p1k);
    gemm_mma<128, true><<<NE / 128, 256, SM128>>>(                              // 7
        (const float*)p1k, (const __nv_bfloat16*)pw2kh, (const __nv_bfloat16*)pw2kl, bk2, (float*)p2k);
    gemm3_fused<8, 4><<<NE / 128, 256, SMF_K>>>(                                // 8
        (const float*)p2k, (const __nv_bfloat16*)pw3kh, (const __nv_bfloat16*)pw3kl,
        bk3, edge_index, edge_sh);

    attn_agg_kernel<<<(NE + 255) / 256, 256>>>(edge_index);                     // 9
    out_stats_kernel<<<(NN + 63) / 64, 256>>>(node_data, W_output);             // 10
    bn_kernel<<<(NN * 64 + 255) / 256, 256>>>(bn_weight, bn_bias, out);         // 11
}

// round 8
// speedup vs baseline: 2.5358x; 1.4064x over previous
#include <cuda_runtime.h>
#include <cuda_bf16.h>
#include <stdint.h>
#include <math.h>

#define NN 10000
#define NE 160000

// ---------------- device scratch (static, allocation-free) ----------------
__device__ float g_t[NN * 16];
__device__ float g_qW[NN * 8];
// transposed, split weights [N, K] bf16
__device__ __nv_bfloat16 g_w1k_h[128 * 32], g_w1k_l[128 * 32];
__device__ __nv_bfloat16 g_w1v_h[128 * 32], g_w1v_l[128 * 32];
__device__ __nv_bfloat16 g_w2k_h[128 * 128], g_w2k_l[128 * 128];
__device__ __nv_bfloat16 g_w2v_h[128 * 128], g_w2v_l[128 * 128];
__device__ __nv_bfloat16 g_w3k_h[512 * 128], g_w3k_l[512 * 128];
__device__ __nv_bfloat16 g_w3v_h[1024 * 128], g_w3v_l[1024 * 128];
// fp32 tail
__device__ float g_vbuf[(size_t)NE * 16];
__device__ float g_logit[NE];
__device__ float g_m[NN];
__device__ float g_z[NN];
__device__ float g_agg[NN * 16];
__device__ float g_colsum[64];
__device__ float g_colsumsq[64];
__device__ float g_outpre[NN * 64];

// ---------------- helpers ----------------
__device__ __forceinline__ void atomicMaxF(float* addr, float v) {
    if (v >= 0.f)
        atomicMax((int*)addr, __float_as_int(v));
    else
        atomicMin((unsigned int*)addr, __float_as_uint(v));
}

__device__ __forceinline__ uint32_t smem_u32(const void* p) {
    uint32_t a;
    asm("{ .reg .u64 t; cvta.to.shared.u64 t, %1; cvt.u32.u64 %0, t; }" : "=r"(a) : "l"(p));
    return a;
}

__device__ __forceinline__ void split2(float x, __nv_bfloat16& h, __nv_bfloat16& l) {
    h = __float2bfloat16(x);
    l = __float2bfloat16(x - __bfloat162float(h));
}

__device__ __forceinline__ void ldm4(uint32_t* r, uint32_t addr) {
    asm volatile("ldmatrix.sync.aligned.m8n8.x4.shared.b16 {%0,%1,%2,%3}, [%4];"
                 : "=r"(r[0]), "=r"(r[1]), "=r"(r[2]), "=r"(r[3]) : "r"(addr));
}

__device__ __forceinline__ void mma16816(float* c, const uint32_t* a, const uint32_t* b) {
    asm volatile(
        "mma.sync.aligned.m16n8k16.row.col.f32.bf16.bf16.f32 "
        "{%0,%1,%2,%3}, {%4,%5,%6,%7}, {%8,%9}, {%0,%1,%2,%3};"
        : "+f"(c[0]), "+f"(c[1]), "+f"(c[2]), "+f"(c[3])
        : "r"(a[0]), "r"(a[1]), "r"(a[2]), "r"(a[3]), "r"(b[0]), "r"(b[1]));
}

// 3-pass split MMA over one [128 x 16*KS] A tile and [128 x 16*KS] B tile
template <int KS, int PITCH>
__device__ __forceinline__ void mma_block(
    uint32_t aH, uint32_t aL, uint32_t bH, uint32_t bL,
    int lane, int wm, int wn, float c[4][4][4])
{
    #pragma unroll
    for (int p = 0; p < 3; p++) {
        uint32_t aB = (p == 2) ? aL : aH;
        uint32_t bB = (p == 1) ? bL : bH;
        #pragma unroll
        for (int kk = 0; kk < KS; kk++) {
            uint32_t a[4][4];
            #pragma unroll
            for (int mt = 0; mt < 4; mt++) {
                int row = wm + mt * 16 + (lane & 15);
                uint32_t addr = aB + ((uint32_t)(row * PITCH + kk * 16 + 8 * (lane >> 4)) << 1);
                ldm4(a[mt], addr);
            }
            uint32_t b[2][4];
            #pragma unroll
            for (int np = 0; np < 2; np++) {
                int row = wn + np * 16 + ((lane >> 4) << 3) + (lane & 7);
                uint32_t addr = bB + ((uint32_t)(row * PITCH + kk * 16 + 8 * ((lane >> 3) & 1)) << 1);
                ldm4(b[np], addr);
            }
            #pragma unroll
            for (int mt = 0; mt < 4; mt++)
                #pragma unroll
                for (int nt = 0; nt < 4; nt++) {
                    uint32_t bb[2] = { b[nt >> 1][(nt & 1) * 2], b[nt >> 1][(nt & 1) * 2 + 1] };
                    mma16816(c[mt][nt], a[mt], bb);
                }
        }
    }
}

// bias + relu + split-store fragments into a [128][136] hi/lo smem tile
__device__ __forceinline__ void epi_split_store(
    float c[4][4][4], const float* __restrict__ bias,
    __nv_bfloat16* Dh, __nv_bfloat16* Dl, int lane, int wm, int wn)
{
    constexpr int P = 136;
    #pragma unroll
    for (int mt = 0; mt < 4; mt++) {
        int r0 = wm + mt * 16 + (lane >> 2);
        #pragma unroll
        for (int nt = 0; nt < 4; nt++) {
            int col = wn + nt * 8 + (lane & 3) * 2;
            float b0 = __ldg(bias + col), b1 = __ldg(bias + col + 1);
            float v0 = fmaxf(c[mt][nt][0] + b0, 0.f);
            float v1 = fmaxf(c[mt][nt][1] + b1, 0.f);
            float v2 = fmaxf(c[mt][nt][2] + b0, 0.f);
            float v3 = fmaxf(c[mt][nt][3] + b1, 0.f);
            __nv_bfloat16 h0, l0, h1, l1;
            split2(v0, h0, l0); split2(v1, h1, l1);
            *(__nv_bfloat162*)&Dh[r0 * P + col] = __nv_bfloat162(h0, h1);
            *(__nv_bfloat162*)&Dl[r0 * P + col] = __nv_bfloat162(l0, l1);
            split2(v2, h0, l0); split2(v3, h1, l1);
            *(__nv_bfloat162*)&Dh[(r0 + 8) * P + col] = __nv_bfloat162(h0, h1);
            *(__nv_bfloat162*)&Dl[(r0 + 8) * P + col] = __nv_bfloat162(l0, l1);
        }
    }
}

// ---------------- weight prep ----------------
__device__ __forceinline__ void wsplit_one(const float* src, __nv_bfloat16* dh,
                                           __nv_bfloat16* dl, int K, int N, int i) {
    int n = i / K, k = i % K;
    __nv_bfloat16 h, l;
    split2(src[k * N + n], h, l);
    dh[i] = h;
    dl[i] = l;
}

__global__ void wsplit_all(const float* __restrict__ Wk1, const float* __restrict__ Wv1,
                           const float* __restrict__ Wk2, const float* __restrict__ Wv2,
                           const float* __restrict__ Wk3, const float* __restrict__ Wv3)
{
    int i = blockIdx.x * 256 + threadIdx.x;
    if (i < 4096) { wsplit_one(Wk1, g_w1k_h, g_w1k_l, 32, 128, i); return; }
    i -= 4096;
    if (i < 4096) { wsplit_one(Wv1, g_w1v_h, g_w1v_l, 32, 128, i); return; }
    i -= 4096;
    if (i < 16384) { wsplit_one(Wk2, g_w2k_h, g_w2k_l, 128, 128, i); return; }
    i -= 16384;
    if (i < 16384) { wsplit_one(Wv2, g_w2v_h, g_w2v_l, 128, 128, i); return; }
    i -= 16384;
    if (i < 65536) { wsplit_one(Wk3, g_w3k_h, g_w3k_l, 128, 512, i); return; }
    i -= 65536;
    if (i < 131072) { wsplit_one(Wv3, g_w3v_h, g_w3v_l, 128, 1024, i); }
}

// ---------------- full MLP chain + contraction, one CTA = 128 edges ----------------
// NOUT=16/NB=8: V path;  NOUT=8/NB=4: K path (logits)
template <int NOUT, int NB>
__global__ __launch_bounds__(256) void chain_fused(
    const float* __restrict__ edge_data,
    const __nv_bfloat16* __restrict__ W1h, const __nv_bfloat16* __restrict__ W1l,
    const float* __restrict__ b1,
    const __nv_bfloat16* __restrict__ W2h, const __nv_bfloat16* __restrict__ W2l,
    const float* __restrict__ b2,
    const __nv_bfloat16* __restrict__ W3h, const __nv_bfloat16* __restrict__ W3l,
    const float* __restrict__ b3,
    const int* __restrict__ ei, const float* __restrict__ sh)
{
    constexpr int P = 136, PA = 40;
    constexpr int NTOT = NB * 128;
    constexpr int NSLOT = (NOUT == 16) ? 4 : 2;
    constexpr int PP = NOUT + 1;
    extern __shared__ char sm[];
    // arena: [0,69632) h1 hi/lo (later u_s+part) | [69632,139264) W2/W3 hi/lo |
    //        [139264,208896) h2 hi/lo (phase-1 scratch first) | [208896,+4KB) bias3
    __nv_bfloat16* H1h = (__nv_bfloat16*)(sm);
    __nv_bfloat16* H1l = (__nv_bfloat16*)(sm + 34816);
    __nv_bfloat16* WBh = (__nv_bfloat16*)(sm + 69632);
    __nv_bfloat16* WBl = (__nv_bfloat16*)(sm + 104448);
    __nv_bfloat16* H2h = (__nv_bfloat16*)(sm + 139264);
    __nv_bfloat16* H2l = (__nv_bfloat16*)(sm + 174080);
    __nv_bfloat16* EAh = (__nv_bfloat16*)(sm + 139264);           // phase-1 scratch
    __nv_bfloat16* EAl = (__nv_bfloat16*)(sm + 149504);
    __nv_bfloat16* W1sh = (__nv_bfloat16*)(sm + 159744);
    __nv_bfloat16* W1sl = (__nv_bfloat16*)(sm + 170000 - 16);     // 169984
    float* u_s = (float*)sm;
    float* part = (float*)(sm + 33280);
    float* bs = (float*)(sm + 208896);

    const int tid = threadIdx.x, lane = tid & 31, warp = tid >> 5;
    const int m0 = blockIdx.x * 128;
    const int wm = (warp >> 2) * 64, wn = (warp & 3) * 32;

    float c[4][4][4];

    // ===== phase 1: h1 = relu(edge @ W1^T + b1) =====
    for (int i = tid; i < 128 * 8; i += 256) {
        int row = i >> 3, c4 = (i & 7) * 4;
        float4 v = *(const float4*)(edge_data + (size_t)(m0 + row) * 32 + c4);
        __nv_bfloat16 h[4], l[4];
        split2(v.x, h[0], l[0]); split2(v.y, h[1], l[1]);
        split2(v.z, h[2], l[2]); split2(v.w, h[3], l[3]);
        *(uint2*)&EAh[row * PA + c4] = *(uint2*)h;
        *(uint2*)&EAl[row * PA + c4] = *(uint2*)l;
    }
    for (int i = tid; i < 128 * 4; i += 256) {
        int row = i >> 2, c8 = (i & 3) * 8;
        *(uint4*)&W1sh[row * PA + c8] = ((const uint4*)W1h)[i];
        *(uint4*)&W1sl[row * PA + c8] = ((const uint4*)W1l)[i];
    }
    __syncthreads();

    #pragma unroll
    for (int mt = 0; mt < 4; mt++)
        #pragma unroll
        for (int nt = 0; nt < 4; nt++)
            #pragma unroll
            for (int j = 0; j < 4; j++) c[mt][nt][j] = 0.f;
    mma_block<2, PA>(smem_u32(EAh), smem_u32(EAl), smem_u32(W1sh), smem_u32(W1sl),
                     lane, wm, wn, c);
    epi_split_store(c, b1, H1h, H1l, lane, wm, wn);

    // ===== phase 2: h2 = relu(h1 @ W2^T + b2) =====
    for (int i = tid; i < 128 * 16; i += 256) {
        int row = i >> 4, c8 = (i & 15) * 8;
        *(uint4*)&WBh[row * P + c8] = ((const uint4*)W2h)[i];
        *(uint4*)&WBl[row * P + c8] = ((const uint4*)W2l)[i];
    }
    __syncthreads();   // h1 stores + W2 loads visible; phase-1 reads of scratch done

    #pragma unroll
    for (int mt = 0; mt < 4; mt++)
        #pragma unroll
        for (int nt = 0; nt < 4; nt++)
            #pragma unroll
            for (int j = 0; j < 4; j++) c[mt][nt][j] = 0.f;
    mma_block<8, P>(smem_u32(H1h), smem_u32(H1l), smem_u32(WBh), smem_u32(WBl),
                    lane, wm, wn, c);
    epi_split_store(c, b2, H2h, H2l, lane, wm, wn);
    __syncthreads();   // all warps done reading h1 (frees region for u_s) and writing h2

    // ===== phase 3: layer-3 GEMM streamed over n-blocks, fused contraction =====
    for (int i = tid; i < 128 * 64; i += 256) {
        int row = i >> 6, as = i & 63;
        int e = m0 + row;
        int src = ei[e];
        u_s[row * 65 + as] = g_t[src * 16 + (as >> 2)] * sh[e * 4 + (as & 3)] * 0.125f;
    }
    for (int i = tid; i < NTOT; i += 256) bs[i] = b3[i];

    float loc[8][NSLOT];
    #pragma unroll
    for (int s = 0; s < 8; s++)
        #pragma unroll
        for (int j = 0; j < NSLOT; j++) loc[s][j] = 0.f;

    const uint32_t sH2h = smem_u32(H2h), sH2l = smem_u32(H2l);
    const uint32_t sWBh = smem_u32(WBh), sWBl = smem_u32(WBl);

    for (int nb = 0; nb < NB; nb++) {
        __syncthreads();   // prev mma done reading WB; (nb=0) u_s/h2 visible
        const uint4* gBh = (const uint4*)(W3h + (size_t)nb * 128 * 128);
        const uint4* gBl = (const uint4*)(W3l + (size_t)nb * 128 * 128);
        for (int i = tid; i < 128 * 16; i += 256) {
            int row = i >> 4, c8 = (i & 15) * 8;
            *(uint4*)&WBh[row * P + c8] = gBh[i];
            *(uint4*)&WBl[row * P + c8] = gBl[i];
        }
        __syncthreads();

        #pragma unroll
        for (int mt = 0; mt < 4; mt++)
            #pragma unroll
            for (int nt = 0; nt < 4; nt++)
                #pragma unroll
                for (int j = 0; j < 4; j++) c[mt][nt][j] = 0.f;
        mma_block<8, P>(sH2h, sH2l, sWBh, sWBl, lane, wm, wn, c);

        #pragma unroll
        for (int mt = 0; mt < 4; mt++) {
            int r = wm + mt * 16 + (lane >> 2);
            #pragma unroll
            for (int nt = 0; nt < 4; nt++) {
                int colb = nb * 128 + wn + nt * 8;
                int as = (NOUT == 16) ? (colb >> 4) : (colb >> 3);
                int obi = (NOUT == 16) ? ((nt & 1) * 2) : 0;
                float ur = u_s[r * 65 + as];
                float ur8 = u_s[(r + 8) * 65 + as];
                loc[mt * 2][obi]         += c[mt][nt][0] * ur;
                loc[mt * 2][obi + 1]     += c[mt][nt][1] * ur;
                loc[mt * 2 + 1][obi]     += c[mt][nt][2] * ur8;
                loc[mt * 2 + 1][obi + 1] += c[mt][nt][3] * ur8;
            }
        }
    }

    // per-warp partials -> smem
    {
        int wi = warp & 3;
        #pragma unroll
        for (int s = 0; s < 8; s++) {
            int row = wm + (s >> 1) * 16 + (s & 1) * 8 + (lane >> 2);
            #pragma unroll
            for (int j = 0; j < NSLOT; j++) {
                int ob = (lane & 3) * 2 + (j & 1) + (j >> 1) * 8;
                part[(wi * 128 + row) * PP + ob] = loc[s][j];
            }
        }
    }
    __syncthreads();

    if (NOUT == 16) {
        for (int idx = tid; idx < 128 * 16; idx += 256) {
            int row = idx >> 4, ob = idx & 15;
            float s = part[row * PP + ob] + part[(128 + row) * PP + ob]
                    + part[(256 + row) * PP + ob] + part[(384 + row) * PP + ob];
            float bt = 0.f;
            #pragma unroll
            for (int as = 0; as < 64; as++) bt = fmaf(u_s[row * 65 + as], bs[as * 16 + ob], bt);
            g_vbuf[(size_t)(m0 + row) * 16 + ob] = s + bt;
        }
    } else {
        for (int idx = tid; idx < 128 * 8; idx += 256) {
            int row = idx >> 3, b = idx & 7;
            float s = part[row * PP + b] + part[(128 + row) * PP + b]
                    + part[(256 + row) * PP + b] + part[(384 + row) * PP + b];
            float bt = 0.f;
            #pragma unroll
            for (int as = 0; as < 64; as++) bt = fmaf(u_s[row * 65 + as], bs[as * 8 + b], bt);
            part[row * PP + b] = s + bt;
        }
        __syncthreads();
        if (tid < 128) {
            int e = m0 + tid;
            int dst = ei[NE + e];
            float lp = 0.f;
            #pragma unroll
            for (int b = 0; b < 8; b++) lp += part[tid * PP + b] * g_qW[dst * 8 + b];
            g_logit[e] = lp;
            atomicMaxF(&g_m[dst], lp);
        }
    }
}

// ---------------- init ----------------
__global__ void init_kernel() {
    int i = blockIdx.x * 256 + threadIdx.x;
    if (i < NN) { g_m[i] = -INFINITY; g_z[i] = 0.f; }
    if (i < NN * 16) g_agg[i] = 0.f;
    if (i < 64) { g_colsum[i] = 0.f; g_colsumsq[i] = 0.f; }
}

// ---------------- node linears ----------------
__global__ __launch_bounds__(128) void node_kernel(
    const float* __restrict__ node_data, const float* __restrict__ W_input,
    const float* __restrict__ W_query, const float* __restrict__ W_dot)
{
    __shared__ float Wi[64 * 16];
    __shared__ float Wq[16 * 8];
    __shared__ float Wd[64];
    __shared__ float tsh[8][16];
    __shared__ float qsh[8][8];
    int tid = threadIdx.x;
    for (int i = tid; i < 1024; i += 128) Wi[i] = W_input[i];
    if (tid < 128) Wq[tid] = W_query[tid];
    if (tid < 64) Wd[tid] = W_dot[tid];
    __syncthreads();

    int n_loc = tid >> 4, c = tid & 15;
    int n = blockIdx.x * 8 + n_loc;
    float tv = 0.f;
    if (n < NN) {
        const float* nd = node_data + (size_t)n * 64;
        #pragma unroll 8
        for (int i = 0; i < 64; i++) tv += nd[i] * Wi[i * 16 + c];
        tv *= 0.125f;
        g_t[n * 16 + c] = tv;
    }
    tsh[n_loc][c] = tv;
    __syncthreads();

    if (tid < 64) {
        int nl = tid >> 3, b = tid & 7;
        float qv = 0.f;
        #pragma unroll
        for (int a = 0; a < 16; a++) qv += tsh[nl][a] * Wq[a * 8 + b];
        qsh[nl][b] = qv * 0.25f;
    }
    __syncthreads();
    if (tid < 64) {
        int nl = tid >> 3, b = tid & 7;
        int n2 = blockIdx.x * 8 + nl;
        if (n2 < NN) {
            float s = 0.f;
            #pragma unroll
            for (int a = 0; a < 8; a++) s += qsh[nl][a] * Wd[a * 8 + b];
            g_qW[n2 * 8 + b] = s * 0.125f;
        }
    }
}

// ---------------- softmax numerator + segment sums ----------------
__global__ void attn_agg_kernel(const int* __restrict__ ei)
{
    int e = blockIdx.x * 256 + threadIdx.x;
    if (e >= NE) return;
    int dst = ei[NE + e];
    float p = expf(g_logit[e] - g_m[dst]);
    atomicAdd(&g_z[dst], p);
    const float* v = g_vbuf + (size_t)e * 16;
    float* agg = g_agg + dst * 16;
    #pragma unroll
    for (int c = 0; c < 16; c++) atomicAdd(&agg[c], p * v[c]);
}

// ---------------- output linear + residual + BN stats ----------------
__global__ __launch_bounds__(256) void out_stats_kernel(
    const float* __restrict__ node_data, const float* __restrict__ W_output)
{
    __shared__ float Wsh[16 * 64];
    __shared__ float red[256];
    int tid = threadIdx.x;
    for (int i = tid; i < 1024; i += 256) Wsh[i] = W_output[i];
    __syncthreads();

    int c = tid & 63;
    int r = tid >> 6;
    int n0 = blockIdx.x * 64;
    float lsum = 0.f, lsq = 0.f;
    for (int i = 0; i < 16; i++) {
        int n = n0 + r + i * 4;
        if (n < NN) {
            float zz = g_z[n];
            float inv = zz > 0.f ? 0.25f / zz : 0.f;
            float o = 0.f;
            const float* agg = g_agg + n * 16;
            #pragma unroll
            for (int j = 0; j < 16; j++) o += agg[j] * Wsh[j * 64 + c];
            o = o * inv + node_data[(size_t)n * 64 + c];
            g_outpre[(size_t)n * 64 + c] = o;
            lsum += o;
            lsq += o * o;
        }
    }
    red[tid] = lsum;
    __syncthreads();
    if (r == 0) atomicAdd(&g_colsum[c], red[c] + red[64 + c] + red[128 + c] + red[192 + c]);
    __syncthreads();
    red[tid] = lsq;
    __syncthreads();
    if (r == 0) atomicAdd(&g_colsumsq[c], red[c] + red[64 + c] + red[128 + c] + red[192 + c]);
}

// ---------------- batchnorm finalize ----------------
__global__ void bn_kernel(const float* __restrict__ bnw, const float* __restrict__ bnb,
                          float* __restrict__ out)
{
    int i = blockIdx.x * 256 + threadIdx.x;
    if (i >= NN * 64) return;
    int c = i & 63;
    const float invN = 1.f / NN;
    float mean = g_colsum[c] * invN;
    float var = g_colsumsq[c] * invN - mean * mean;
    out[i] = (g_outpre[i] - mean) * rsqrtf(var + 1e-5f) * bnw[c] + bnb[c];
}

// ---------------- launch ----------------
extern "C" void kernel_launch(void* const* d_in, const int* in_sizes, int n_in,
                              void* d_out, int out_size)
{
    const float* node_data = (const float*)d_in[0];
    const int*   edge_index = (const int*)d_in[1];
    const float* edge_data = (const float*)d_in[2];
    const float* edge_sh   = (const float*)d_in[3];
    const float* W_input = (const float*)d_in[4];
    const float* W_query = (const float*)d_in[5];
    const float* W_dot   = (const float*)d_in[6];
    const float* W_output = (const float*)d_in[7];
    const float* Wk1 = (const float*)d_in[8];
    const float* bk1 = (const float*)d_in[9];
    const float* Wk2 = (const float*)d_in[10];
    const float* bk2 = (const float*)d_in[11];
    const float* Wk3 = (const float*)d_in[12];
    const float* bk3 = (const float*)d_in[13];
    const float* Wv1 = (const float*)d_in[14];
    const float* bv1 = (const float*)d_in[15];
    const float* Wv2 = (const float*)d_in[16];
    const float* bv2 = (const float*)d_in[17];
    const float* Wv3 = (const float*)d_in[18];
    const float* bv3 = (const float*)d_in[19];
    const float* bn_weight = (const float*)d_in[20];
    const float* bn_bias   = (const float*)d_in[21];
    float* out = (float*)d_out;

    void *pw1kh, *pw1kl, *pw1vh, *pw1vl, *pw2kh, *pw2kl, *pw2vh, *pw2vl;
    void *pw3kh, *pw3kl, *pw3vh, *pw3vl;
    cudaGetSymbolAddress(&pw1kh, g_w1k_h); cudaGetSymbolAddress(&pw1kl, g_w1k_l);
    cudaGetSymbolAddress(&pw1vh, g_w1v_h); cudaGetSymbolAddress(&pw1vl, g_w1v_l);
    cudaGetSymbolAddress(&pw2kh, g_w2k_h); cudaGetSymbolAddress(&pw2kl, g_w2k_l);
    cudaGetSymbolAddress(&pw2vh, g_w2v_h); cudaGetSymbolAddress(&pw2vl, g_w2v_l);
    cudaGetSymbolAddress(&pw3kh, g_w3k_h); cudaGetSymbolAddress(&pw3kl, g_w3k_l);
    cudaGetSymbolAddress(&pw3vh, g_w3v_h); cudaGetSymbolAddress(&pw3vl, g_w3v_l);

    const int SMC = 208896 + 4096;   // 212992
    cudaFuncSetAttribute(chain_fused<16, 8>, cudaFuncAttributeMaxDynamicSharedMemorySize, SMC);
    cudaFuncSetAttribute(chain_fused<8, 4>, cudaFuncAttributeMaxDynamicSharedMemorySize, SMC);

    init_kernel<<<(NE + 255) / 256, 256>>>();                                   // 0
    wsplit_all<<<(237568 + 255) / 256, 256>>>(Wk1, Wv1, Wk2, Wv2, Wk3, Wv3);    // 1
    node_kernel<<<(NN + 7) / 8, 128>>>(node_data, W_input, W_query, W_dot);     // 2
    chain_fused<16, 8><<<NE / 128, 256, SMC>>>(                                 // 3 (V)
        edge_data,
        (const __nv_bfloat16*)pw1vh, (const __nv_bfloat16*)pw1vl, bv1,
        (const __nv_bfloat16*)pw2vh, (const __nv_bfloat16*)pw2vl, bv2,
        (const __nv_bfloat16*)pw3vh, (const __nv_bfloat16*)pw3vl, bv3,
        edge_index, edge_sh);
    chain_fused<8, 4><<<NE / 128, 256, SMC>>>(                                  // 4 (K)
        edge_data,
        (const __nv_bfloat16*)pw1kh, (const __nv_bfloat16*)pw1kl, bk1,
        (const __nv_bfloat16*)pw2kh, (const __nv_bfloat16*)pw2kl, bk2,
        (const __nv_bfloat16*)pw3kh, (const __nv_bfloat16*)pw3kl, bk3,
        edge_index, edge_sh);

    attn_agg_kernel<<<(NE + 255) / 256, 256>>>(edge_index);                     // 5
    out_stats_kernel<<<(NN + 63) / 64, 256>>>(node_data, W_output);             // 6
    bn_kernel<<<(NN * 64 + 255) / 256, 256>>>(bn_weight, bn_bias, out);         // 7
}

// round 9
// speedup vs baseline: 2.7731x; 1.0935x over previous
#include <cuda_runtime.h>
#include <cuda_bf16.h>
#include <stdint.h>
#include <math.h>

#define NN 10000
#define NE 160000

// ---------------- device scratch (static, allocation-free) ----------------
__device__ float g_t[NN * 16];
__device__ float g_qW[NN * 8];
// transposed, split weights [N, K] bf16
__device__ __nv_bfloat16 g_w1k_h[128 * 32], g_w1k_l[128 * 32];
__device__ __nv_bfloat16 g_w1v_h[128 * 32], g_w1v_l[128 * 32];
__device__ __nv_bfloat16 g_w2k_h[128 * 128], g_w2k_l[128 * 128];
__device__ __nv_bfloat16 g_w2v_h[128 * 128], g_w2v_l[128 * 128];
__device__ __nv_bfloat16 g_w3k_h[512 * 128], g_w3k_l[512 * 128];
__device__ __nv_bfloat16 g_w3v_h[1024 * 128], g_w3v_l[1024 * 128];
// fp32 tail
__device__ float g_vbuf[(size_t)NE * 16];
__device__ float g_logit[NE];
__device__ float g_m[NN];
__device__ float g_z[NN];
__device__ float g_agg[NN * 16];
__device__ float g_colsum[64];
__device__ float g_colsumsq[64];
__device__ float g_outpre[NN * 64];

// ---------------- helpers ----------------
__device__ __forceinline__ void atomicMaxF(float* addr, float v) {
    if (v >= 0.f)
        atomicMax((int*)addr, __float_as_int(v));
    else
        atomicMin((unsigned int*)addr, __float_as_uint(v));
}

__device__ __forceinline__ uint32_t smem_u32(const void* p) {
    uint32_t a;
    asm("{ .reg .u64 t; cvta.to.shared.u64 t, %1; cvt.u32.u64 %0, t; }" : "=r"(a) : "l"(p));
    return a;
}

__device__ __forceinline__ void split2(float x, __nv_bfloat16& h, __nv_bfloat16& l) {
    h = __float2bfloat16(x);
    l = __float2bfloat16(x - __bfloat162float(h));
}

__device__ __forceinline__ void ldm4(uint32_t* r, uint32_t addr) {
    asm volatile("ldmatrix.sync.aligned.m8n8.x4.shared.b16 {%0,%1,%2,%3}, [%4];"
                 : "=r"(r[0]), "=r"(r[1]), "=r"(r[2]), "=r"(r[3]) : "r"(addr));
}

__device__ __forceinline__ void mma16816(float* c, const uint32_t* a, const uint32_t* b) {
    asm volatile(
        "mma.sync.aligned.m16n8k16.row.col.f32.bf16.bf16.f32 "
        "{%0,%1,%2,%3}, {%4,%5,%6,%7}, {%8,%9}, {%0,%1,%2,%3};"
        : "+f"(c[0]), "+f"(c[1]), "+f"(c[2]), "+f"(c[3])
        : "r"(a[0]), "r"(a[1]), "r"(a[2]), "r"(a[3]), "r"(b[0]), "r"(b[1]));
}

// 3-term split MMA with fragments hoisted across the passes:
// per k-step: 12 ldsm -> 48 mma (Ah*Bh + Ah*Bl + Al*Bh into the same fp32 acc)
template <int KS, int PITCH>
__device__ __forceinline__ void mma_block(
    uint32_t aH, uint32_t aL, uint32_t bH, uint32_t bL,
    int lane, int wm, int wn, float c[4][4][4])
{
    #pragma unroll
    for (int kk = 0; kk < KS; kk++) {
        uint32_t ah[4][4], al[4][4], bh[2][4], bl[2][4];
        #pragma unroll
        for (int mt = 0; mt < 4; mt++) {
            int row = wm + mt * 16 + (lane & 15);
            uint32_t off = (uint32_t)(row * PITCH + kk * 16 + 8 * (lane >> 4)) << 1;
            ldm4(ah[mt], aH + off);
            ldm4(al[mt], aL + off);
        }
        #pragma unroll
        for (int np = 0; np < 2; np++) {
            int row = wn + np * 16 + ((lane >> 4) << 3) + (lane & 7);
            uint32_t off = (uint32_t)(row * PITCH + kk * 16 + 8 * ((lane >> 3) & 1)) << 1;
            ldm4(bh[np], bH + off);
            ldm4(bl[np], bL + off);
        }
        #pragma unroll
        for (int mt = 0; mt < 4; mt++)
            #pragma unroll
            for (int nt = 0; nt < 4; nt++) {
                uint32_t bbh[2] = { bh[nt >> 1][(nt & 1) * 2], bh[nt >> 1][(nt & 1) * 2 + 1] };
                uint32_t bbl[2] = { bl[nt >> 1][(nt & 1) * 2], bl[nt >> 1][(nt & 1) * 2 + 1] };
                mma16816(c[mt][nt], ah[mt], bbh);
                mma16816(c[mt][nt], ah[mt], bbl);
                mma16816(c[mt][nt], al[mt], bbh);
            }
    }
}

// bias + relu + split-store fragments into a [128][136] hi/lo smem tile
__device__ __forceinline__ void epi_split_store(
    float c[4][4][4], const float* __restrict__ bias,
    __nv_bfloat16* Dh, __nv_bfloat16* Dl, int lane, int wm, int wn)
{
    constexpr int P = 136;
    #pragma unroll
    for (int mt = 0; mt < 4; mt++) {
        int r0 = wm + mt * 16 + (lane >> 2);
        #pragma unroll
        for (int nt = 0; nt < 4; nt++) {
            int col = wn + nt * 8 + (lane & 3) * 2;
            float b0 = __ldg(bias + col), b1 = __ldg(bias + col + 1);
            float v0 = fmaxf(c[mt][nt][0] + b0, 0.f);
            float v1 = fmaxf(c[mt][nt][1] + b1, 0.f);
            float v2 = fmaxf(c[mt][nt][2] + b0, 0.f);
            float v3 = fmaxf(c[mt][nt][3] + b1, 0.f);
            __nv_bfloat16 h0, l0, h1, l1;
            split2(v0, h0, l0); split2(v1, h1, l1);
            *(__nv_bfloat162*)&Dh[r0 * P + col] = __nv_bfloat162(h0, h1);
            *(__nv_bfloat162*)&Dl[r0 * P + col] = __nv_bfloat162(l0, l1);
            split2(v2, h0, l0); split2(v3, h1, l1);
            *(__nv_bfloat162*)&Dh[(r0 + 8) * P + col] = __nv_bfloat162(h0, h1);
            *(__nv_bfloat162*)&Dl[(r0 + 8) * P + col] = __nv_bfloat162(l0, l1);
        }
    }
}

// ---------------- weight prep ----------------
__device__ __forceinline__ void wsplit_one(const float* src, __nv_bfloat16* dh,
                                           __nv_bfloat16* dl, int K, int N, int i) {
    int n = i / K, k = i % K;
    __nv_bfloat16 h, l;
    split2(src[k * N + n], h, l);
    dh[i] = h;
    dl[i] = l;
}

__global__ void wsplit_all(const float* __restrict__ Wk1, const float* __restrict__ Wv1,
                           const float* __restrict__ Wk2, const float* __restrict__ Wv2,
                           const float* __restrict__ Wk3, const float* __restrict__ Wv3)
{
    int i = blockIdx.x * 256 + threadIdx.x;
    if (i < 4096) { wsplit_one(Wk1, g_w1k_h, g_w1k_l, 32, 128, i); return; }
    i -= 4096;
    if (i < 4096) { wsplit_one(Wv1, g_w1v_h, g_w1v_l, 32, 128, i); return; }
    i -= 4096;
    if (i < 16384) { wsplit_one(Wk2, g_w2k_h, g_w2k_l, 128, 128, i); return; }
    i -= 16384;
    if (i < 16384) { wsplit_one(Wv2, g_w2v_h, g_w2v_l, 128, 128, i); return; }
    i -= 16384;
    if (i < 65536) { wsplit_one(Wk3, g_w3k_h, g_w3k_l, 128, 512, i); return; }
    i -= 65536;
    if (i < 131072) { wsplit_one(Wv3, g_w3v_h, g_w3v_l, 128, 1024, i); }
}

// ---------------- full MLP chain + contraction (device body) ----------------
// NOUT=16/NB=8: V path;  NOUT=8/NB=4: K path (logits)
template <int NOUT, int NB>
__device__ __forceinline__ void chain_body(
    char* sm,
    const float* __restrict__ edge_data,
    const __nv_bfloat16* __restrict__ W1h, const __nv_bfloat16* __restrict__ W1l,
    const float* __restrict__ b1,
    const __nv_bfloat16* __restrict__ W2h, const __nv_bfloat16* __restrict__ W2l,
    const float* __restrict__ b2,
    const __nv_bfloat16* __restrict__ W3h, const __nv_bfloat16* __restrict__ W3l,
    const float* __restrict__ b3,
    const int* __restrict__ ei, const float* __restrict__ sh)
{
    constexpr int P = 136, PA = 40;
    constexpr int NTOT = NB * 128;
    constexpr int NSLOT = (NOUT == 16) ? 4 : 2;
    constexpr int PP = NOUT + 1;
    __nv_bfloat16* H1h = (__nv_bfloat16*)(sm);
    __nv_bfloat16* H1l = (__nv_bfloat16*)(sm + 34816);
    __nv_bfloat16* WBh = (__nv_bfloat16*)(sm + 69632);
    __nv_bfloat16* WBl = (__nv_bfloat16*)(sm + 104448);
    __nv_bfloat16* H2h = (__nv_bfloat16*)(sm + 139264);
    __nv_bfloat16* H2l = (__nv_bfloat16*)(sm + 174080);
    __nv_bfloat16* EAh = (__nv_bfloat16*)(sm + 139264);           // phase-1 scratch
    __nv_bfloat16* EAl = (__nv_bfloat16*)(sm + 149504);
    __nv_bfloat16* W1sh = (__nv_bfloat16*)(sm + 159744);
    __nv_bfloat16* W1sl = (__nv_bfloat16*)(sm + 169984);
    float* u_s = (float*)sm;
    float* part = (float*)(sm + 33280);
    float* bs = (float*)(sm + 208896);

    const int tid = threadIdx.x, lane = tid & 31, warp = tid >> 5;
    const int m0 = blockIdx.x * 128;
    const int wm = (warp >> 2) * 64, wn = (warp & 3) * 32;

    float c[4][4][4];

    // ===== phase 1: h1 = relu(edge @ W1^T + b1) =====
    for (int i = tid; i < 128 * 8; i += 256) {
        int row = i >> 3, c4 = (i & 7) * 4;
        float4 v = *(const float4*)(edge_data + (size_t)(m0 + row) * 32 + c4);
        __nv_bfloat16 h[4], l[4];
        split2(v.x, h[0], l[0]); split2(v.y, h[1], l[1]);
        split2(v.z, h[2], l[2]); split2(v.w, h[3], l[3]);
        *(uint2*)&EAh[row * PA + c4] = *(uint2*)h;
        *(uint2*)&EAl[row * PA + c4] = *(uint2*)l;
    }
    for (int i = tid; i < 128 * 4; i += 256) {
        int row = i >> 2, c8 = (i & 3) * 8;
        *(uint4*)&W1sh[row * PA + c8] = ((const uint4*)W1h)[i];
        *(uint4*)&W1sl[row * PA + c8] = ((const uint4*)W1l)[i];
    }
    __syncthreads();

    #pragma unroll
    for (int mt = 0; mt < 4; mt++)
        #pragma unroll
        for (int nt = 0; nt < 4; nt++)
            #pragma unroll
            for (int j = 0; j < 4; j++) c[mt][nt][j] = 0.f;
    mma_block<2, PA>(smem_u32(EAh), smem_u32(EAl), smem_u32(W1sh), smem_u32(W1sl),
                     lane, wm, wn, c);
    epi_split_store(c, b1, H1h, H1l, lane, wm, wn);

    // ===== phase 2: h2 = relu(h1 @ W2^T + b2) =====
    for (int i = tid; i < 128 * 16; i += 256) {
        int row = i >> 4, c8 = (i & 15) * 8;
        *(uint4*)&WBh[row * P + c8] = ((const uint4*)W2h)[i];
        *(uint4*)&WBl[row * P + c8] = ((const uint4*)W2l)[i];
    }
    __syncthreads();

    #pragma unroll
    for (int mt = 0; mt < 4; mt++)
        #pragma unroll
        for (int nt = 0; nt < 4; nt++)
            #pragma unroll
            for (int j = 0; j < 4; j++) c[mt][nt][j] = 0.f;
    mma_block<8, P>(smem_u32(H1h), smem_u32(H1l), smem_u32(WBh), smem_u32(WBl),
                    lane, wm, wn, c);
    epi_split_store(c, b2, H2h, H2l, lane, wm, wn);
    __syncthreads();   // all warps done reading h1 (frees region for u_s) and writing h2

    // ===== phase 3: layer-3 GEMM streamed over n-blocks, fused contraction =====
    for (int i = tid; i < 128 * 64; i += 256) {
        int row = i >> 6, as = i & 63;
        int e = m0 + row;
        int src = ei[e];
        u_s[row * 65 + as] = g_t[src * 16 + (as >> 2)] * sh[e * 4 + (as & 3)] * 0.125f;
    }
    for (int i = tid; i < NTOT; i += 256) bs[i] = b3[i];

    float loc[8][NSLOT];
    #pragma unroll
    for (int s = 0; s < 8; s++)
        #pragma unroll
        for (int j = 0; j < NSLOT; j++) loc[s][j] = 0.f;

    const uint32_t sH2h = smem_u32(H2h), sH2l = smem_u32(H2l);
    const uint32_t sWBh = smem_u32(WBh), sWBl = smem_u32(WBl);

    for (int nb = 0; nb < NB; nb++) {
        __syncthreads();
        const uint4* gBh = (const uint4*)(W3h + (size_t)nb * 128 * 128);
        const uint4* gBl = (const uint4*)(W3l + (size_t)nb * 128 * 128);
        for (int i = tid; i < 128 * 16; i += 256) {
            int row = i >> 4, c8 = (i & 15) * 8;
            *(uint4*)&WBh[row * P + c8] = gBh[i];
            *(uint4*)&WBl[row * P + c8] = gBl[i];
        }
        __syncthreads();

        #pragma unroll
        for (int mt = 0; mt < 4; mt++)
            #pragma unroll
            for (int nt = 0; nt < 4; nt++)
                #pragma unroll
                for (int j = 0; j < 4; j++) c[mt][nt][j] = 0.f;
        mma_block<8, P>(sH2h, sH2l, sWBh, sWBl, lane, wm, wn, c);

        #pragma unroll
        for (int mt = 0; mt < 4; mt++) {
            int r = wm + mt * 16 + (lane >> 2);
            #pragma unroll
            for (int nt = 0; nt < 4; nt++) {
                int colb = nb * 128 + wn + nt * 8;
                int as = (NOUT == 16) ? (colb >> 4) : (colb >> 3);
                int obi = (NOUT == 16) ? ((nt & 1) * 2) : 0;
                float ur = u_s[r * 65 + as];
                float ur8 = u_s[(r + 8) * 65 + as];
                loc[mt * 2][obi]         += c[mt][nt][0] * ur;
                loc[mt * 2][obi + 1]     += c[mt][nt][1] * ur;
                loc[mt * 2 + 1][obi]     += c[mt][nt][2] * ur8;
                loc[mt * 2 + 1][obi + 1] += c[mt][nt][3] * ur8;
            }
        }
    }

    // per-warp partials -> smem
    {
        int wi = warp & 3;
        #pragma unroll
        for (int s = 0; s < 8; s++) {
            int row = wm + (s >> 1) * 16 + (s & 1) * 8 + (lane >> 2);
            #pragma unroll
            for (int j = 0; j < NSLOT; j++) {
                int ob = (lane & 3) * 2 + (j & 1) + (j >> 1) * 8;
                part[(wi * 128 + row) * PP + ob] = loc[s][j];
            }
        }
    }
    __syncthreads();

    if (NOUT == 16) {
        for (int idx = tid; idx < 128 * 16; idx += 256) {
            int row = idx >> 4, ob = idx & 15;
            float s = part[row * PP + ob] + part[(128 + row) * PP + ob]
                    + part[(256 + row) * PP + ob] + part[(384 + row) * PP + ob];
            float bt = 0.f;
            #pragma unroll
            for (int as = 0; as < 64; as++) bt = fmaf(u_s[row * 65 + as], bs[as * 16 + ob], bt);
            g_vbuf[(size_t)(m0 + row) * 16 + ob] = s + bt;
        }
    } else {
        for (int idx = tid; idx < 128 * 8; idx += 256) {
            int row = idx >> 3, b = idx & 7;
            float s = part[row * PP + b] + part[(128 + row) * PP + b]
                    + part[(256 + row) * PP + b] + part[(384 + row) * PP + b];
            float bt = 0.f;
            #pragma unroll
            for (int as = 0; as < 64; as++) bt = fmaf(u_s[row * 65 + as], bs[as * 8 + b], bt);
            part[row * PP + b] = s + bt;
        }
        __syncthreads();
        if (tid < 128) {
            int e = m0 + tid;
            int dst = ei[NE + e];
            float lp = 0.f;
            #pragma unroll
            for (int b = 0; b < 8; b++) lp += part[tid * PP + b] * g_qW[dst * 8 + b];
            g_logit[e] = lp;
            atomicMaxF(&g_m[dst], lp);
        }
    }
}

// one kernel runs the V chain then the K chain on the same 128 edges
__global__ __launch_bounds__(256) void chain_both(
    const float* __restrict__ edge_data,
    const __nv_bfloat16* __restrict__ Wv1h, const __nv_bfloat16* __restrict__ Wv1l,
    const float* __restrict__ bv1,
    const __nv_bfloat16* __restrict__ Wv2h, const __nv_bfloat16* __restrict__ Wv2l,
    const float* __restrict__ bv2,
    const __nv_bfloat16* __restrict__ Wv3h, const __nv_bfloat16* __restrict__ Wv3l,
    const float* __restrict__ bv3,
    const __nv_bfloat16* __restrict__ Wk1h, const __nv_bfloat16* __restrict__ Wk1l,
    const float* __restrict__ bk1,
    const __nv_bfloat16* __restrict__ Wk2h, const __nv_bfloat16* __restrict__ Wk2l,
    const float* __restrict__ bk2,
    const __nv_bfloat16* __restrict__ Wk3h, const __nv_bfloat16* __restrict__ Wk3l,
    const float* __restrict__ bk3,
    const int* __restrict__ ei, const float* __restrict__ sh)
{
    extern __shared__ char sm[];
    chain_body<16, 8>(sm, edge_data, Wv1h, Wv1l, bv1, Wv2h, Wv2l, bv2,
                      Wv3h, Wv3l, bv3, ei, sh);
    __syncthreads();
    chain_body<8, 4>(sm, edge_data, Wk1h, Wk1l, bk1, Wk2h, Wk2l, bk2,
                     Wk3h, Wk3l, bk3, ei, sh);
}

// ---------------- init ----------------
__global__ void init_kernel() {
    int i = blockIdx.x * 256 + threadIdx.x;
    if (i < NN) { g_m[i] = -INFINITY; g_z[i] = 0.f; }
    if (i < NN * 16) g_agg[i] = 0.f;
    if (i < 64) { g_colsum[i] = 0.f; g_colsumsq[i] = 0.f; }
}

// ---------------- node linears ----------------
__global__ __launch_bounds__(128) void node_kernel(
    const float* __restrict__ node_data, const float* __restrict__ W_input,
    const float* __restrict__ W_query, const float* __restrict__ W_dot)
{
    __shared__ float Wi[64 * 16];
    __shared__ float Wq[16 * 8];
    __shared__ float Wd[64];
    __shared__ float tsh[8][16];
    __shared__ float qsh[8][8];
    int tid = threadIdx.x;
    for (int i = tid; i < 1024; i += 128) Wi[i] = W_input[i];
    if (tid < 128) Wq[tid] = W_query[tid];
    if (tid < 64) Wd[tid] = W_dot[tid];
    __syncthreads();

    int n_loc = tid >> 4, c = tid & 15;
    int n = blockIdx.x * 8 + n_loc;
    float tv = 0.f;
    if (n < NN) {
        const float* nd = node_data + (size_t)n * 64;
        #pragma unroll 8
        for (int i = 0; i < 64; i++) tv += nd[i] * Wi[i * 16 + c];
        tv *= 0.125f;
        g_t[n * 16 + c] = tv;
    }
    tsh[n_loc][c] = tv;
    __syncthreads();

    if (tid < 64) {
        int nl = tid >> 3, b = tid & 7;
        float qv = 0.f;
        #pragma unroll
        for (int a = 0; a < 16; a++) qv += tsh[nl][a] * Wq[a * 8 + b];
        qsh[nl][b] = qv * 0.25f;
    }
    __syncthreads();
    if (tid < 64) {
        int nl = tid >> 3, b = tid & 7;
        int n2 = blockIdx.x * 8 + nl;
        if (n2 < NN) {
            float s = 0.f;
            #pragma unroll
            for (int a = 0; a < 8; a++) s += qsh[nl][a] * Wd[a * 8 + b];
            g_qW[n2 * 8 + b] = s * 0.125f;
        }
    }
}

// ---------------- softmax numerator + segment sums ----------------
__global__ void attn_agg_kernel(const int* __restrict__ ei)
{
    int e = blockIdx.x * 256 + threadIdx.x;
    if (e >= NE) return;
    int dst = ei[NE + e];
    float p = expf(g_logit[e] - g_m[dst]);
    atomicAdd(&g_z[dst], p);
    const float* v = g_vbuf + (size_t)e * 16;
    float* agg = g_agg + dst * 16;
    #pragma unroll
    for (int c = 0; c < 16; c++) atomicAdd(&agg[c], p * v[c]);
}

// ---------------- output linear + residual + BN stats ----------------
__global__ __launch_bounds__(256) void out_stats_kernel(
    const float* __restrict__ node_data, const float* __restrict__ W_output)
{
    __shared__ float Wsh[16 * 64];
    __shared__ float red[256];
    int tid = threadIdx.x;
    for (int i = tid; i < 1024; i += 256) Wsh[i] = W_output[i];
    __syncthreads();

    int c = tid & 63;
    int r = tid >> 6;
    int n0 = blockIdx.x * 64;
    float lsum = 0.f, lsq = 0.f;
    for (int i = 0; i < 16; i++) {
        int n = n0 + r + i * 4;
        if (n < NN) {
            float zz = g_z[n];
            float inv = zz > 0.f ? 0.25f / zz : 0.f;
            float o = 0.f;
            const float* agg = g_agg + n * 16;
            #pragma unroll
            for (int j = 0; j < 16; j++) o += agg[j] * Wsh[j * 64 + c];
            o = o * inv + node_data[(size_t)n * 64 + c];
            g_outpre[(size_t)n * 64 + c] = o;
            lsum += o;
            lsq += o * o;
        }
    }
    red[tid] = lsum;
    __syncthreads();
    if (r == 0) atomicAdd(&g_colsum[c], red[c] + red[64 + c] + red[128 + c] + red[192 + c]);
    __syncthreads();
    red[tid] = lsq;
    __syncthreads();
    if (r == 0) atomicAdd(&g_colsumsq[c], red[c] + red[64 + c] + red[128 + c] + red[192 + c]);
}

// ---------------- batchnorm finalize ----------------
__global__ void bn_kernel(const float* __restrict__ bnw, const float* __restrict__ bnb,
                          float* __restrict__ out)
{
    int i = blockIdx.x * 256 + threadIdx.x;
    if (i >= NN * 64) return;
    int c = i & 63;
    const float invN = 1.f / NN;
    float mean = g_colsum[c] * invN;
    float var = g_colsumsq[c] * invN - mean * mean;
    out[i] = (g_outpre[i] - mean) * rsqrtf(var + 1e-5f) * bnw[c] + bnb[c];
}

// ---------------- launch ----------------
extern "C" void kernel_launch(void* const* d_in, const int* in_sizes, int n_in,
                              void* d_out, int out_size)
{
    const float* node_data = (const float*)d_in[0];
    const int*   edge_index = (const int*)d_in[1];
    const float* edge_data = (const float*)d_in[2];
    const float* edge_sh   = (const float*)d_in[3];
    const float* W_input = (const float*)d_in[4];
    const float* W_query = (const float*)d_in[5];
    const float* W_dot   = (const float*)d_in[6];
    const float* W_output = (const float*)d_in[7];
    const float* Wk1 = (const float*)d_in[8];
    const float* bk1 = (const float*)d_in[9];
    const float* Wk2 = (const float*)d_in[10];
    const float* bk2 = (const float*)d_in[11];
    const float* Wk3 = (const float*)d_in[12];
    const float* bk3 = (const float*)d_in[13];
    const float* Wv1 = (const float*)d_in[14];
    const float* bv1 = (const float*)d_in[15];
    const float* Wv2 = (const float*)d_in[16];
    const float* bv2 = (const float*)d_in[17];
    const float* Wv3 = (const float*)d_in[18];
    const float* bv3 = (const float*)d_in[19];
    const float* bn_weight = (const float*)d_in[20];
    const float* bn_bias   = (const float*)d_in[21];
    float* out = (float*)d_out;

    void *pw1kh, *pw1kl, *pw1vh, *pw1vl, *pw2kh, *pw2kl, *pw2vh, *pw2vl;
    void *pw3kh, *pw3kl, *pw3vh, *pw3vl;
    cudaGetSymbolAddress(&pw1kh, g_w1k_h); cudaGetSymbolAddress(&pw1kl, g_w1k_l);
    cudaGetSymbolAddress(&pw1vh, g_w1v_h); cudaGetSymbolAddress(&pw1vl, g_w1v_l);
    cudaGetSymbolAddress(&pw2kh, g_w2k_h); cudaGetSymbolAddress(&pw2kl, g_w2k_l);
    cudaGetSymbolAddress(&pw2vh, g_w2v_h); cudaGetSymbolAddress(&pw2vl, g_w2v_l);
    cudaGetSymbolAddress(&pw3kh, g_w3k_h); cudaGetSymbolAddress(&pw3kl, g_w3k_l);
    cudaGetSymbolAddress(&pw3vh, g_w3v_h); cudaGetSymbolAddress(&pw3vl, g_w3v_l);

    const int SMC = 208896 + 4096;   // 212992
    cudaFuncSetAttribute(chain_both, cudaFuncAttributeMaxDynamicSharedMemorySize, SMC);

    init_kernel<<<(NE + 255) / 256, 256>>>();                                   // 0
    wsplit_all<<<(237568 + 255) / 256, 256>>>(Wk1, Wv1, Wk2, Wv2, Wk3, Wv3);    // 1
    node_kernel<<<(NN + 7) / 8, 128>>>(node_data, W_input, W_query, W_dot);     // 2
    chain_both<<<NE / 128, 256, SMC>>>(                                         // 3
        edge_data,
        (const __nv_bfloat16*)pw1vh, (const __nv_bfloat16*)pw1vl, bv1,
        (const __nv_bfloat16*)pw2vh, (const __nv_bfloat16*)pw2vl, bv2,
        (const __nv_bfloat16*)pw3vh, (const __nv_bfloat16*)pw3vl, bv3,
        (const __nv_bfloat16*)pw1kh, (const __nv_bfloat16*)pw1kl, bk1,
        (const __nv_bfloat16*)pw2kh, (const __nv_bfloat16*)pw2kl, bk2,
        (const __nv_bfloat16*)pw3kh, (const __nv_bfloat16*)pw3kl, bk3,
        edge_index, edge_sh);

    attn_agg_kernel<<<(NE + 255) / 256, 256>>>(edge_index);                     // 4
    out_stats_kernel<<<(NN + 63) / 64, 256>>>(node_data, W_output);             // 5
    bn_kernel<<<(NN * 64 + 255) / 256, 256>>>(bn_weight, bn_bias, out);         // 6
}